// round 14
// baseline (speedup 1.0000x reference)
#include <cuda_runtime.h>
#include <cuda_fp16.h>
#include <math.h>
#include <stdint.h>

// Problem dims (fixed)
#define BB 2
#define SS 2048
#define DD 1024
#define HH 16
#define DHH 64
#define FF 4096
#define NTOK (BB*SS)   // 4096

// ---------------- scratch (device globals) -----------------------------------
__device__ __half g_h  [NTOK*DD];
__device__ __half g_q  [NTOK*DD];
__device__ __half g_k  [NTOK*DD];
__device__ __half g_v  [NTOK*DD];
__device__ __half g_o  [NTOK*DD];
__device__ float  g_add1[NTOK*DD];
__device__ __half g_h2 [NTOK*DD];
__device__ __half g_act[NTOK*FF];
__device__ __half g_wqkv[3*DD*DD];     // concatenated [3*DD, DD] row-major ([N,K])
__device__ __half g_wo[DD*DD];
__device__ __half g_w1[DD*FF], g_w2[FF*DD];

// ---------------- helpers ------------------------------------------------------
__device__ __forceinline__ uint32_t smem_u32(const void* p) {
    uint32_t a;
    asm("{ .reg .u64 t; cvta.to.shared.u64 t, %1; cvt.u32.u64 %0, t; }" : "=r"(a) : "l"(p));
    return a;
}
__device__ __forceinline__ void cp_async16(uint32_t dst, const void* src) {
    asm volatile("cp.async.cg.shared.global [%0], [%1], 16;"
                 :: "r"(dst), "l"(src) : "memory");
}
__device__ __forceinline__ void cp_commit() {
    asm volatile("cp.async.commit_group;" ::: "memory");
}
template<int N>
__device__ __forceinline__ void cp_wait() {
    asm volatile("cp.async.wait_group %0;" :: "n"(N) : "memory");
}
__device__ __forceinline__ void ldsm_x4(uint32_t* r, uint32_t addr) {
    asm volatile("ldmatrix.sync.aligned.m8n8.x4.shared.b16 {%0,%1,%2,%3}, [%4];"
                 : "=r"(r[0]), "=r"(r[1]), "=r"(r[2]), "=r"(r[3]) : "r"(addr));
}
__device__ __forceinline__ void ldsm_x4_t(uint32_t* r, uint32_t addr) {
    asm volatile("ldmatrix.sync.aligned.m8n8.x4.trans.shared.b16 {%0,%1,%2,%3}, [%4];"
                 : "=r"(r[0]), "=r"(r[1]), "=r"(r[2]), "=r"(r[3]) : "r"(addr));
}
__device__ __forceinline__ void mma16816h(float* d, const uint32_t* a, const uint32_t* b) {
    asm volatile(
        "mma.sync.aligned.m16n8k16.row.col.f32.f16.f16.f32 "
        "{%0,%1,%2,%3}, {%4,%5,%6,%7}, {%8,%9}, {%0,%1,%2,%3};"
        : "+f"(d[0]), "+f"(d[1]), "+f"(d[2]), "+f"(d[3])
        : "r"(a[0]), "r"(a[1]), "r"(a[2]), "r"(a[3]), "r"(b[0]), "r"(b[1]));
}
__device__ __forceinline__ uint32_t packh(float a, float b) {
    __half2 t = __floats2half2_rn(a, b);
    return *reinterpret_cast<uint32_t*>(&t);
}

// ---------------- fused prologue: ln1 rows + all weight transposes --------------
__global__ void prologue_kernel(const float* __restrict__ x,
                                const float* __restrict__ g,
                                const float* __restrict__ b,
                                __half* __restrict__ y,
                                const float* __restrict__ wq, const float* __restrict__ wk,
                                const float* __restrict__ wv, const float* __restrict__ wo,
                                const float* __restrict__ w1, const float* __restrict__ w2,
                                __half* __restrict__ oqkv, __half* __restrict__ oo,
                                __half* __restrict__ o1, __half* __restrict__ o2) {
    const int tid = threadIdx.x;
    if (blockIdx.x < NTOK) {
        const int row = blockIdx.x;
        const float* xr = x + (size_t)row * DD;
        float v[4];
        float s = 0.f, s2 = 0.f;
#pragma unroll
        for (int i = 0; i < 4; ++i) {
            v[i] = xr[tid + i * 256];
            s += v[i]; s2 += v[i] * v[i];
        }
        for (int off = 16; off > 0; off >>= 1) {
            s  += __shfl_down_sync(0xffffffffu, s,  off);
            s2 += __shfl_down_sync(0xffffffffu, s2, off);
        }
        __shared__ float rs[8], rs2[8];
        if ((tid & 31) == 0) { rs[tid >> 5] = s; rs2[tid >> 5] = s2; }
        __syncthreads();
        if (tid < 8) { s = rs[tid]; s2 = rs2[tid]; } else { s = 0.f; s2 = 0.f; }
        if (tid < 32) {
            for (int off = 4; off > 0; off >>= 1) {
                s  += __shfl_down_sync(0xffffffffu, s,  off);
                s2 += __shfl_down_sync(0xffffffffu, s2, off);
            }
            if (tid == 0) { rs[0] = s; rs2[0] = s2; }
        }
        __syncthreads();
        const float mean = rs[0] * (1.0f / DD);
        const float var  = rs2[0] * (1.0f / DD) - mean * mean;
        const float inv  = rsqrtf(var + 1e-5f);
        __half* yr = y + (size_t)row * DD;
#pragma unroll
        for (int i = 0; i < 4; ++i) {
            const int c = tid + i * 256;
            yr[c] = __float2half_rn((v[i] - mean) * inv * g[c] + b[c]);
        }
        return;
    }

    int id = blockIdx.x - NTOK;
    const float* w; __half* dst; int K, N;
    if (id < 4096) {
        const int sel = id >> 10; id &= 1023;
        K = DD; N = DD;
        w   = (sel == 0) ? wq : (sel == 1) ? wk : (sel == 2) ? wv : wo;
        dst = (sel == 3) ? oo : oqkv + (size_t)sel * DD * DD;
    } else if (id < 8192) {
        id -= 4096; K = DD; N = FF; w = w1; dst = o1;
    } else {
        id -= 8192; K = FF; N = DD; w = w2; dst = o2;
    }
    const int ntx = N >> 5;
    const int bx = id % ntx;
    const int by = id / ntx;

    __shared__ float t[32][33];
    const int tx = tid & 31;
    const int ty = tid >> 5;
#pragma unroll
    for (int i = 0; i < 32; i += 8)
        t[ty + i][tx] = w[(size_t)(by * 32 + ty + i) * N + bx * 32 + tx];
    __syncthreads();
#pragma unroll
    for (int i = 0; i < 32; i += 8) {
        const int n = bx * 32 + ty + i;
        const int k = by * 32 + tx;
        dst[(size_t)n * K + k] = __float2half_rn(t[tx][ty + i]);
    }
}

// ---------------- fp16 GEMM: C[M,N] = A[M,K] @ B^T ([N,K] fp16) -----------------
// Single fp16 x fp16, fp32 accumulate. CTA 128x128, BK=64, 4 warps (2m x 2n),
// warp tile 64x64 (32 indep MMA / 8 ldsm per kstep). 128 threads, 3-stage ring.
#define ROWB 144
#define TILESZ (128*ROWB)      // 18432
#define STAGE  (2*TILESZ)      // 36864 (A,B)
#define GEMM_SMEM (3*STAGE + 512)   // 111104

__device__ __forceinline__ void issue_chunk64(const __half* const* tp, int k0,
                                              uint32_t buf, int tid, int K) {
#pragma unroll
    for (int t = 0; t < 2; ++t) {
#pragma unroll
        for (int u = 0; u < 8; ++u) {
            const int lin = tid + u * 128;       // 0..1023
            const int r = lin >> 3;              // 0..127
            const int c8 = lin & 7;              // 16B chunk (128B data row)
            const void* src = tp[t] + (size_t)r * K + k0 + c8 * 8;
            cp_async16(buf + t * TILESZ + r * ROWB + c8 * 16, src);
        }
    }
    cp_commit();
}

template<int OUTMODE /*0=f32, 2=fp16*/, bool HAS_RES, bool DO_GELU, bool SPLIT3>
__global__ void __launch_bounds__(128, 2)
tc_gemm(const __half* __restrict__ A, const __half* __restrict__ B,
        const float* __restrict__ bias, const float* __restrict__ bias1,
        const float* __restrict__ bias2,
        const float* __restrict__ res,
        float* __restrict__ Cf,
        __half* __restrict__ Ch, __half* __restrict__ Ch1, __half* __restrict__ Ch2,
        int M, int N, int K) {
    extern __shared__ char smem[];
    const uint32_t sbase = smem_u32(smem);
    float* bias_s = (float*)(smem + 3 * STAGE);

    const int tid  = threadIdx.x;
    const int wid  = tid >> 5;
    const int lane = tid & 31;
    const int wm = wid >> 1;        // 0..1 (m)
    const int wn = wid & 1;         // 0..1 (n)
    const int bx = blockIdx.x, by = blockIdx.y;

    const float* bp = bias;
    __half* chp = Ch;
    int nout = N;
    int ncol0 = bx * 128;
    if (SPLIT3) {
        const int seg = bx >> 3;
        bp  = (seg == 0) ? bias : (seg == 1) ? bias1 : bias2;
        chp = (seg == 0) ? Ch   : (seg == 1) ? Ch1   : Ch2;
        nout = DD;
        ncol0 = (bx & 7) * 128;
    }
    bias_s[tid] = bp[ncol0 + tid];

    const size_t aoff = (size_t)by * 128 * K;
    const size_t boff = (size_t)bx * 128 * K;
    const __half* tp[2] = { A + aoff, B + boff };

    const int nchunk = K >> 6;   // BK=64

    float acc[4][8][4];
#pragma unroll
    for (int mt = 0; mt < 4; ++mt)
#pragma unroll
        for (int nt = 0; nt < 8; ++nt)
#pragma unroll
            for (int e = 0; e < 4; ++e) acc[mt][nt][e] = 0.f;

    const int a_row = wm * 64 + (lane & 15);
    const int a_kof = (lane >> 4) << 3;
    const int b_row = wn * 64 + (lane & 7) + ((lane >> 4) << 3);
    const int b_kof = ((lane >> 3) & 1) << 3;

    issue_chunk64(tp, 0, sbase, tid, K);
    issue_chunk64(tp, 64, sbase + STAGE, tid, K);

    int st = 0;
    for (int i = 0; i < nchunk; ++i) {
        if (i + 1 < nchunk) cp_wait<1>(); else cp_wait<0>();
        __syncthreads();
        if (i + 2 < nchunk) {
            int st2 = st + 2; if (st2 >= 3) st2 -= 3;
            issue_chunk64(tp, (i + 2) << 6, sbase + st2 * STAGE, tid, K);
        }

        const uint32_t buf = sbase + st * STAGE;
        const uint32_t aA = buf + a_row * ROWB;
        const uint32_t aB = buf + TILESZ + b_row * ROWB;

#pragma unroll
        for (int ks = 0; ks < 4; ++ks) {
            const int ak = (ks * 16 + a_kof) * 2;
            const int bk = (ks * 16 + b_kof) * 2;
            uint32_t bh[8][2];
#pragma unroll
            for (int p = 0; p < 4; ++p) {
                uint32_t r[4];
                ldsm_x4(r, aB + p * 16 * ROWB + bk);
                bh[2*p][0] = r[0]; bh[2*p][1] = r[1];
                bh[2*p+1][0] = r[2]; bh[2*p+1][1] = r[3];
            }
            uint32_t ah[4][4];
#pragma unroll
            for (int mt = 0; mt < 4; ++mt)
                ldsm_x4(ah[mt], aA + mt * 16 * ROWB + ak);
#pragma unroll
            for (int mt = 0; mt < 4; ++mt)
#pragma unroll
                for (int nt = 0; nt < 8; ++nt)
                    mma16816h(acc[mt][nt], ah[mt], bh[nt]);
        }
        if (++st == 3) st = 0;
    }
    __syncthreads();

    const int mbase = by * 128 + wm * 64;
    const int nloc0 = wn * 64;
#pragma unroll
    for (int mt = 0; mt < 4; ++mt) {
#pragma unroll
        for (int half = 0; half < 2; ++half) {
            const int m = mbase + mt * 16 + (lane >> 2) + half * 8;
#pragma unroll
            for (int nt = 0; nt < 8; ++nt) {
                const int nloc = nloc0 + nt * 8 + 2 * (lane & 3);
                const int n = ncol0 + nloc;
                float v0 = acc[mt][nt][half * 2 + 0] + bias_s[nloc];
                float v1 = acc[mt][nt][half * 2 + 1] + bias_s[nloc + 1];
                if (DO_GELU) {
                    v0 = 0.5f * v0 * (1.0f + erff(v0 * 0.70710678118654752f));
                    v1 = 0.5f * v1 * (1.0f + erff(v1 * 0.70710678118654752f));
                }
                if (HAS_RES) {
                    const float2 rv = *(const float2*)(res + (size_t)m * nout + n);
                    v0 += rv.x; v1 += rv.y;
                }
                if (OUTMODE == 0) {
                    *(float2*)(Cf + (size_t)m * nout + n) = make_float2(v0, v1);
                } else {
                    *(__half2*)(chp + (size_t)m * nout + n) = __floats2half2_rn(v0, v1);
                }
            }
        }
    }
}

// ---------------- Flash attention (fp16, causal), double-buffered KV ------------
#define AROWB 144
#define KVSTAGE (128*AROWB)                 // K tile + V tile = 18432
#define ATT_SMEM (128*AROWB + 2*KVSTAGE)    // Q + 2 KV stages = 55296

__global__ void __launch_bounds__(256, 2)
attn_mma(const __half* __restrict__ q, const __half* __restrict__ k,
         const __half* __restrict__ v, __half* __restrict__ o) {
    extern __shared__ char sm[];
    const uint32_t sb = smem_u32(sm);
    const uint32_t sQ = sb;
    const uint32_t sKV = sb + 128 * AROWB;

    const int qt = gridDim.x - 1 - blockIdx.x;   // big tiles first
    const int bh = blockIdx.y;
    const int b = bh >> 4, h = bh & 15;
    const size_t base = (size_t)b * SS * DD + (size_t)h * DHH;
    const int q0 = qt * 128;

    const int tid = threadIdx.x, warp = tid >> 5, lane = tid & 31;

#pragma unroll
    for (int u = 0; u < 4; ++u) {
        const int lin = tid + u * 256;
        const int r = lin >> 3, c = lin & 7;
        cp_async16(sQ + r * AROWB + c * 16, q + base + (size_t)(q0 + r) * DD + c * 8);
    }
    cp_commit();

    {
        const __half* srck = k + base;
        const __half* srcv = v + base;
#pragma unroll
        for (int u = 0; u < 2; ++u) {
            const int lin = tid + u * 256;
            const int rr = lin >> 3, cc = lin & 7;
            const size_t go = (size_t)rr * DD + cc * 8;
            const uint32_t so = rr * AROWB + cc * 16;
            cp_async16(sKV + so, srck + go);
            cp_async16(sKV + 64 * AROWB + so, srcv + go);
        }
        cp_commit();
    }

    float sfr[8][4], oac[8][4];
    float m0 = -1e30f, m1 = -1e30f, l0 = 0.f, l1 = 0.f;
#pragma unroll
    for (int j = 0; j < 8; ++j)
#pragma unroll
        for (int e = 0; e < 4; ++e) oac[j][e] = 0.f;

    const uint32_t qb = sQ + (warp * 16 + (lane & 15)) * AROWB + (((lane >> 4) << 3) << 1);
    const int krow = (lane & 7) + ((lane >> 4) << 3);
    const uint32_t kof = (((lane >> 3) & 1) << 3) << 1;
    const int vrow = lane & 15;
    const uint32_t vof = (((lane >> 4) << 3)) << 1;

    const int ntile = qt * 2 + 2;
    for (int kt = 0; kt < ntile; ++kt) {
        cp_wait<0>();
        __syncthreads();
        if (kt + 1 < ntile) {
            const int k1 = (kt + 1) * 64;
            const uint32_t dst = sKV + ((kt + 1) & 1) * KVSTAGE;
            const __half* srck = k + base + (size_t)k1 * DD;
            const __half* srcv = v + base + (size_t)k1 * DD;
#pragma unroll
            for (int u = 0; u < 2; ++u) {
                const int lin = tid + u * 256;
                const int rr = lin >> 3, cc = lin & 7;
                const size_t go = (size_t)rr * DD + cc * 8;
                const uint32_t so = rr * AROWB + cc * 16;
                cp_async16(dst + so, srck + go);
                cp_async16(dst + 64 * AROWB + so, srcv + go);
            }
            cp_commit();
        }

        const uint32_t sK = sKV + (kt & 1) * KVSTAGE;
        const uint32_t sV = sK + 64 * AROWB;
        const int k0 = kt * 64;

#pragma unroll
        for (int j = 0; j < 8; ++j)
#pragma unroll
            for (int e = 0; e < 4; ++e) sfr[j][e] = 0.f;
#pragma unroll
        for (int t = 0; t < 4; ++t) {
            uint32_t qa[4];
            ldsm_x4(qa, qb + t * 32);
#pragma unroll
            for (int g = 0; g < 4; ++g) {
                uint32_t kb[4];
                ldsm_x4(kb, sK + (g * 16 + krow) * AROWB + t * 32 + kof);
                mma16816h(sfr[2*g],   qa, kb);
                mma16816h(sfr[2*g+1], qa, kb + 2);
            }
        }

        const float cs = 0.1803368801111204f;   // 0.125 * log2(e)
        const int rg0 = q0 + warp * 16 + (lane >> 2);
        if (kt >= 2 * qt) {
#pragma unroll
            for (int j = 0; j < 8; ++j) {
                const int cb = k0 + j * 8 + 2 * (lane & 3);
#pragma unroll
                for (int e = 0; e < 4; ++e) {
                    const int cg = cb + (e & 1);
                    const int rg = rg0 + ((e >> 1) << 3);
                    const float s = sfr[j][e] * cs;
                    sfr[j][e] = (cg > rg) ? -1e30f : s;
                }
            }
        } else {
#pragma unroll
            for (int j = 0; j < 8; ++j)
#pragma unroll
                for (int e = 0; e < 4; ++e) sfr[j][e] *= cs;
        }
        float mx0 = -1e30f, mx1 = -1e30f;
#pragma unroll
        for (int j = 0; j < 8; ++j) {
            mx0 = fmaxf(mx0, fmaxf(sfr[j][0], sfr[j][1]));
            mx1 = fmaxf(mx1, fmaxf(sfr[j][2], sfr[j][3]));
        }
        mx0 = fmaxf(mx0, __shfl_xor_sync(0xffffffffu, mx0, 1));
        mx0 = fmaxf(mx0, __shfl_xor_sync(0xffffffffu, mx0, 2));
        mx1 = fmaxf(mx1, __shfl_xor_sync(0xffffffffu, mx1, 1));
        mx1 = fmaxf(mx1, __shfl_xor_sync(0xffffffffu, mx1, 2));
        mx0 = fmaxf(mx0, m0);
        mx1 = fmaxf(mx1, m1);
        const float al0 = exp2f(m0 - mx0);
        const float al1 = exp2f(m1 - mx1);
        m0 = mx0; m1 = mx1;
        float s0 = 0.f, s1 = 0.f;
#pragma unroll
        for (int j = 0; j < 8; ++j) {
            float p0 = exp2f(sfr[j][0] - mx0);
            float p1 = exp2f(sfr[j][1] - mx0);
            float p2 = exp2f(sfr[j][2] - mx1);
            float p3 = exp2f(sfr[j][3] - mx1);
            sfr[j][0] = p0; sfr[j][1] = p1; sfr[j][2] = p2; sfr[j][3] = p3;
            s0 += p0 + p1; s1 += p2 + p3;
        }
        s0 += __shfl_xor_sync(0xffffffffu, s0, 1);
        s0 += __shfl_xor_sync(0xffffffffu, s0, 2);
        s1 += __shfl_xor_sync(0xffffffffu, s1, 1);
        s1 += __shfl_xor_sync(0xffffffffu, s1, 2);
        l0 = l0 * al0 + s0;
        l1 = l1 * al1 + s1;
#pragma unroll
        for (int j = 0; j < 8; ++j) {
            oac[j][0] *= al0; oac[j][1] *= al0;
            oac[j][2] *= al1; oac[j][3] *= al1;
        }

#pragma unroll
        for (int t = 0; t < 4; ++t) {
            const float* f0 = sfr[2*t];
            const float* f1 = sfr[2*t+1];
            uint32_t pa[4];
            pa[0] = packh(f0[0], f0[1]);
            pa[1] = packh(f0[2], f0[3]);
            pa[2] = packh(f1[0], f1[1]);
            pa[3] = packh(f1[2], f1[3]);
#pragma unroll
            for (int np = 0; np < 4; ++np) {
                uint32_t vb[4];
                ldsm_x4_t(vb, sV + (t * 16 + vrow) * AROWB + np * 32 + vof);
                mma16816h(oac[2*np],   pa, vb);
                mma16816h(oac[2*np+1], pa, vb + 2);
            }
        }
    }

    const float inv0 = 1.f / l0, inv1 = 1.f / l1;
    const int r0g = q0 + warp * 16 + (lane >> 2);
#pragma unroll
    for (int j = 0; j < 8; ++j) {
        const size_t off0 = base + (size_t)r0g * DD + j * 8 + 2 * (lane & 3);
        const size_t off1 = off0 + (size_t)8 * DD;
        *(__half2*)(o + off0) = __floats2half2_rn(oac[j][0] * inv0, oac[j][1] * inv0);
        *(__half2*)(o + off1) = __floats2half2_rn(oac[j][2] * inv1, oac[j][3] * inv1);
    }
}

// ---------------- LayerNorm -> fp16 (standalone, for ln2) -----------------------
__global__ void ln_half_kernel(const float* __restrict__ x,
                               const float* __restrict__ g,
                               const float* __restrict__ b,
                               __half* __restrict__ y) {
    const int row = blockIdx.x;
    const int tid = threadIdx.x;
    const float* xr = x + (size_t)row * DD;

    float v[4];
    float s = 0.f, s2 = 0.f;
#pragma unroll
    for (int i = 0; i < 4; ++i) {
        v[i] = xr[tid + i * 256];
        s += v[i]; s2 += v[i] * v[i];
    }
    for (int off = 16; off > 0; off >>= 1) {
        s  += __shfl_down_sync(0xffffffffu, s,  off);
        s2 += __shfl_down_sync(0xffffffffu, s2, off);
    }
    __shared__ float rs[8], rs2[8];
    if ((tid & 31) == 0) { rs[tid >> 5] = s; rs2[tid >> 5] = s2; }
    __syncthreads();
    if (tid < 8) { s = rs[tid]; s2 = rs2[tid]; } else { s = 0.f; s2 = 0.f; }
    if (tid < 32) {
        for (int off = 4; off > 0; off >>= 1) {
            s  += __shfl_down_sync(0xffffffffu, s,  off);
            s2 += __shfl_down_sync(0xffffffffu, s2, off);
        }
        if (tid == 0) { rs[0] = s; rs2[0] = s2; }
    }
    __syncthreads();
    const float mean = rs[0] * (1.0f / DD);
    const float var  = rs2[0] * (1.0f / DD) - mean * mean;
    const float inv  = rsqrtf(var + 1e-5f);
    __half* yr = y + (size_t)row * DD;
#pragma unroll
    for (int i = 0; i < 4; ++i) {
        const int c = tid + i * 256;
        yr[c] = __float2half_rn((v[i] - mean) * inv * g[c] + b[c]);
    }
}

// ---------------- host launcher -------------------------------------------------
extern "C" void kernel_launch(void* const* d_in, const int* in_sizes, int n_in,
                              void* d_out, int out_size) {
    const float* x     = (const float*)d_in[0];
    const float* ln1_g = (const float*)d_in[1];
    const float* ln1_b = (const float*)d_in[2];
    const float* wq    = (const float*)d_in[3];
    const float* bq    = (const float*)d_in[4];
    const float* wk    = (const float*)d_in[5];
    const float* bk    = (const float*)d_in[6];
    const float* wv    = (const float*)d_in[7];
    const float* bv    = (const float*)d_in[8];
    const float* wo    = (const float*)d_in[9];
    const float* bo    = (const float*)d_in[10];
    const float* ln2_g = (const float*)d_in[11];
    const float* ln2_b = (const float*)d_in[12];
    const float* w1    = (const float*)d_in[13];
    const float* b1    = (const float*)d_in[14];
    const float* w2    = (const float*)d_in[15];
    const float* b2    = (const float*)d_in[16];
    float* out = (float*)d_out;

    __half *ph, *pq, *pk, *pv, *po, *ph2, *pact;
    __half *pwqkv, *pwo, *pw1, *pw2;
    float *padd1;
    cudaGetSymbolAddress((void**)&ph,   g_h);
    cudaGetSymbolAddress((void**)&pq,   g_q);
    cudaGetSymbolAddress((void**)&pk,   g_k);
    cudaGetSymbolAddress((void**)&pv,   g_v);
    cudaGetSymbolAddress((void**)&po,   g_o);
    cudaGetSymbolAddress((void**)&padd1,g_add1);
    cudaGetSymbolAddress((void**)&ph2,  g_h2);
    cudaGetSymbolAddress((void**)&pact, g_act);
    cudaGetSymbolAddress((void**)&pwqkv,g_wqkv);
    cudaGetSymbolAddress((void**)&pwo,  g_wo);
    cudaGetSymbolAddress((void**)&pw1,  g_w1);
    cudaGetSymbolAddress((void**)&pw2,  g_w2);

    cudaFuncSetAttribute(tc_gemm<2,false,false,true >, cudaFuncAttributeMaxDynamicSharedMemorySize, GEMM_SMEM);
    cudaFuncSetAttribute(tc_gemm<0,true, false,false>, cudaFuncAttributeMaxDynamicSharedMemorySize, GEMM_SMEM);
    cudaFuncSetAttribute(tc_gemm<2,false,true ,false>, cudaFuncAttributeMaxDynamicSharedMemorySize, GEMM_SMEM);
    cudaFuncSetAttribute(attn_mma, cudaFuncAttributeMaxDynamicSharedMemorySize, ATT_SMEM);

    dim3 gridD(DD/128, NTOK/128);
    dim3 gridF(FF/128, NTOK/128);

    // #1 fused prologue: ln1 (4096 blocks) + all weight transposes (12288 blocks)
    prologue_kernel<<<NTOK + 12288, 256>>>(x, ln1_g, ln1_b, ph,
                                           wq, wk, wv, wo, w1, w2,
                                           pwqkv, pwo, pw1, pw2);

    // #2 fused QKV GEMM (768 CTAs, SPLIT3 output routing)
    {
        dim3 grid(3*DD/128, NTOK/128);
        tc_gemm<2,false,false,true><<<grid, 128, GEMM_SMEM>>>(
            ph, pwqkv, bq, bk, bv, nullptr,
            nullptr, pq, pk, pv, NTOK, 3*DD, DD);
    }

    // #3 attention
    {
        dim3 grid(SS/128, BB*HH);
        attn_mma<<<grid, 256, ATT_SMEM>>>(pq, pk, pv, po);
    }

    // #4 O-proj + residual: add1 = x + o@wo + bo
    tc_gemm<0,true,false,false><<<gridD, 128, GEMM_SMEM>>>(
        po, pwo, bo, nullptr, nullptr, x,
        padd1, nullptr, nullptr, nullptr, NTOK, DD, DD);

    // #5 ln2
    ln_half_kernel<<<NTOK, 256>>>(padd1, ln2_g, ln2_b, ph2);

    // #6 MLP up + gelu -> fp16
    tc_gemm<2,false,true,false><<<gridF, 128, GEMM_SMEM>>>(
        ph2, pw1, b1, nullptr, nullptr, nullptr,
        nullptr, pact, nullptr, nullptr, NTOK, FF, DD);

    // #7 MLP down + residual -> out
    tc_gemm<0,true,false,false><<<gridD, 128, GEMM_SMEM>>>(
        pact, pw2, b2, nullptr, nullptr, padd1,
        out, nullptr, nullptr, nullptr, NTOK, DD, FF);
}

// round 15
// speedup vs baseline: 1.0423x; 1.0423x over previous
#include <cuda_runtime.h>
#include <cuda_fp16.h>
#include <math.h>
#include <stdint.h>

// Problem dims (fixed)
#define BB 2
#define SS 2048
#define DD 1024
#define HH 16
#define DHH 64
#define FF 4096
#define NTOK (BB*SS)   // 4096

// ---------------- scratch (device globals) -----------------------------------
__device__ __half g_h  [NTOK*DD];
__device__ __half g_q  [NTOK*DD];
__device__ __half g_k  [NTOK*DD];
__device__ __half g_v  [NTOK*DD];
__device__ __half g_o  [NTOK*DD];
__device__ float  g_add1[NTOK*DD];
__device__ __half g_h2 [NTOK*DD];
__device__ __half g_act[NTOK*FF];
__device__ __half g_wqkv[3*DD*DD];     // concatenated [3*DD, DD] row-major ([N,K])
__device__ __half g_wo[DD*DD];
__device__ __half g_w1[DD*FF], g_w2[FF*DD];

// ---------------- helpers ------------------------------------------------------
__device__ __forceinline__ uint32_t smem_u32(const void* p) {
    uint32_t a;
    asm("{ .reg .u64 t; cvta.to.shared.u64 t, %1; cvt.u32.u64 %0, t; }" : "=r"(a) : "l"(p));
    return a;
}
__device__ __forceinline__ void cp_async16(uint32_t dst, const void* src) {
    asm volatile("cp.async.cg.shared.global [%0], [%1], 16;"
                 :: "r"(dst), "l"(src) : "memory");
}
__device__ __forceinline__ void cp_commit() {
    asm volatile("cp.async.commit_group;" ::: "memory");
}
template<int N>
__device__ __forceinline__ void cp_wait() {
    asm volatile("cp.async.wait_group %0;" :: "n"(N) : "memory");
}
__device__ __forceinline__ void ldsm_x4(uint32_t* r, uint32_t addr) {
    asm volatile("ldmatrix.sync.aligned.m8n8.x4.shared.b16 {%0,%1,%2,%3}, [%4];"
                 : "=r"(r[0]), "=r"(r[1]), "=r"(r[2]), "=r"(r[3]) : "r"(addr));
}
__device__ __forceinline__ void ldsm_x4_t(uint32_t* r, uint32_t addr) {
    asm volatile("ldmatrix.sync.aligned.m8n8.x4.trans.shared.b16 {%0,%1,%2,%3}, [%4];"
                 : "=r"(r[0]), "=r"(r[1]), "=r"(r[2]), "=r"(r[3]) : "r"(addr));
}
__device__ __forceinline__ void mma16816h(float* d, const uint32_t* a, const uint32_t* b) {
    asm volatile(
        "mma.sync.aligned.m16n8k16.row.col.f32.f16.f16.f32 "
        "{%0,%1,%2,%3}, {%4,%5,%6,%7}, {%8,%9}, {%0,%1,%2,%3};"
        : "+f"(d[0]), "+f"(d[1]), "+f"(d[2]), "+f"(d[3])
        : "r"(a[0]), "r"(a[1]), "r"(a[2]), "r"(a[3]), "r"(b[0]), "r"(b[1]));
}
__device__ __forceinline__ uint32_t packh(float a, float b) {
    __half2 t = __floats2half2_rn(a, b);
    return *reinterpret_cast<uint32_t*>(&t);
}

// ---------------- fused prologue: ln1 rows + all weight transposes --------------
// blocks [0, NTOK): LayerNorm row -> fp16.
// blocks [NTOK, NTOK+12288): 32x32 weight transpose tiles (qkv concat, wo, w1, w2).
__global__ void prologue_kernel(const float* __restrict__ x,
                                const float* __restrict__ g,
                                const float* __restrict__ b,
                                __half* __restrict__ y,
                                const float* __restrict__ wq, const float* __restrict__ wk,
                                const float* __restrict__ wv, const float* __restrict__ wo,
                                const float* __restrict__ w1, const float* __restrict__ w2,
                                __half* __restrict__ oqkv, __half* __restrict__ oo,
                                __half* __restrict__ o1, __half* __restrict__ o2) {
    const int tid = threadIdx.x;
    if (blockIdx.x < NTOK) {
        // -------- LayerNorm row --------
        const int row = blockIdx.x;
        const float* xr = x + (size_t)row * DD;
        float v[4];
        float s = 0.f, s2 = 0.f;
#pragma unroll
        for (int i = 0; i < 4; ++i) {
            v[i] = xr[tid + i * 256];
            s += v[i]; s2 += v[i] * v[i];
        }
        for (int off = 16; off > 0; off >>= 1) {
            s  += __shfl_down_sync(0xffffffffu, s,  off);
            s2 += __shfl_down_sync(0xffffffffu, s2, off);
        }
        __shared__ float rs[8], rs2[8];
        if ((tid & 31) == 0) { rs[tid >> 5] = s; rs2[tid >> 5] = s2; }
        __syncthreads();
        if (tid < 8) { s = rs[tid]; s2 = rs2[tid]; } else { s = 0.f; s2 = 0.f; }
        if (tid < 32) {
            for (int off = 4; off > 0; off >>= 1) {
                s  += __shfl_down_sync(0xffffffffu, s,  off);
                s2 += __shfl_down_sync(0xffffffffu, s2, off);
            }
            if (tid == 0) { rs[0] = s; rs2[0] = s2; }
        }
        __syncthreads();
        const float mean = rs[0] * (1.0f / DD);
        const float var  = rs2[0] * (1.0f / DD) - mean * mean;
        const float inv  = rsqrtf(var + 1e-5f);
        __half* yr = y + (size_t)row * DD;
#pragma unroll
        for (int i = 0; i < 4; ++i) {
            const int c = tid + i * 256;
            yr[c] = __float2half_rn((v[i] - mean) * inv * g[c] + b[c]);
        }
        return;
    }

    // -------- weight transpose tile --------
    int id = blockIdx.x - NTOK;
    const float* w; __half* dst; int K, N;
    if (id < 4096) {
        const int sel = id >> 10; id &= 1023;
        K = DD; N = DD;
        w   = (sel == 0) ? wq : (sel == 1) ? wk : (sel == 2) ? wv : wo;
        dst = (sel == 3) ? oo : oqkv + (size_t)sel * DD * DD;
    } else if (id < 8192) {
        id -= 4096; K = DD; N = FF; w = w1; dst = o1;
    } else {
        id -= 8192; K = FF; N = DD; w = w2; dst = o2;
    }
    const int ntx = N >> 5;
    const int bx = id % ntx;
    const int by = id / ntx;

    __shared__ float t[32][33];
    const int tx = tid & 31;
    const int ty = tid >> 5;
#pragma unroll
    for (int i = 0; i < 32; i += 8)
        t[ty + i][tx] = w[(size_t)(by * 32 + ty + i) * N + bx * 32 + tx];
    __syncthreads();
#pragma unroll
    for (int i = 0; i < 32; i += 8) {
        const int n = bx * 32 + ty + i;
        const int k = by * 32 + tx;
        dst[(size_t)n * K + k] = __float2half_rn(t[tx][ty + i]);
    }
}

// ---------------- fp16 GEMM: C[M,N] = A[M,K] @ B^T ([N,K] fp16) -----------------
// Single fp16 x fp16, fp32 accumulate. CTA 128x128, BK=64, 8 warps (2m x 4n),
// warp tile 64x32. 3-stage ring. SPLIT3 routes output thirds to q/k/v buffers.
#define ROWB 144
#define TILESZ (128*ROWB)      // 18432
#define STAGE  (2*TILESZ)      // 36864 (A,B)
#define GEMM_SMEM (3*STAGE + 512)   // 111104

__device__ __forceinline__ void issue_chunk64(const __half* const* tp, int k0,
                                              uint32_t buf, int tid, int K) {
#pragma unroll
    for (int t = 0; t < 2; ++t) {
#pragma unroll
        for (int u = 0; u < 4; ++u) {
            const int lin = tid + u * 256;
            const int r = lin >> 3;
            const int c8 = lin & 7;
            const void* src = tp[t] + (size_t)r * K + k0 + c8 * 8;
            cp_async16(buf + t * TILESZ + r * ROWB + c8 * 16, src);
        }
    }
    cp_commit();
}

template<int OUTMODE /*0=f32, 2=fp16*/, bool HAS_RES, bool DO_GELU, bool SPLIT3>
__global__ void __launch_bounds__(256, 2)
tc_gemm(const __half* __restrict__ A, const __half* __restrict__ B,
        const float* __restrict__ bias, const float* __restrict__ bias1,
        const float* __restrict__ bias2,
        const float* __restrict__ res,
        float* __restrict__ Cf,
        __half* __restrict__ Ch, __half* __restrict__ Ch1, __half* __restrict__ Ch2,
        int M, int N, int K) {
    extern __shared__ char smem[];
    const uint32_t sbase = smem_u32(smem);
    float* bias_s = (float*)(smem + 3 * STAGE);

    const int tid  = threadIdx.x;
    const int wid  = tid >> 5;
    const int lane = tid & 31;
    const int wm = wid >> 2;        // 0..1 (m)
    const int wn = wid & 3;         // 0..3 (n)
    const int bx = blockIdx.x, by = blockIdx.y;

    const float* bp = bias;
    __half* chp = Ch;
    int nout = N;
    int ncol0 = bx * 128;
    if (SPLIT3) {
        const int seg = bx >> 3;
        bp  = (seg == 0) ? bias : (seg == 1) ? bias1 : bias2;
        chp = (seg == 0) ? Ch   : (seg == 1) ? Ch1   : Ch2;
        nout = DD;
        ncol0 = (bx & 7) * 128;
    }
    if (tid < 128) bias_s[tid] = bp[ncol0 + tid];

    const size_t aoff = (size_t)by * 128 * K;
    const size_t boff = (size_t)bx * 128 * K;
    const __half* tp[2] = { A + aoff, B + boff };

    const int nchunk = K >> 6;   // BK=64

    float acc[4][4][4];
#pragma unroll
    for (int mt = 0; mt < 4; ++mt)
#pragma unroll
        for (int nt = 0; nt < 4; ++nt)
#pragma unroll
            for (int e = 0; e < 4; ++e) acc[mt][nt][e] = 0.f;

    const int a_row = wm * 64 + (lane & 15);
    const int a_kof = (lane >> 4) << 3;
    const int b_row = wn * 32 + (lane & 7) + ((lane >> 4) << 3);
    const int b_kof = ((lane >> 3) & 1) << 3;

    issue_chunk64(tp, 0, sbase, tid, K);
    issue_chunk64(tp, 64, sbase + STAGE, tid, K);

    int st = 0;
    for (int i = 0; i < nchunk; ++i) {
        if (i + 1 < nchunk) cp_wait<1>(); else cp_wait<0>();
        __syncthreads();
        if (i + 2 < nchunk) {
            int st2 = st + 2; if (st2 >= 3) st2 -= 3;
            issue_chunk64(tp, (i + 2) << 6, sbase + st2 * STAGE, tid, K);
        }

        const uint32_t buf = sbase + st * STAGE;
        const uint32_t aA = buf + a_row * ROWB;
        const uint32_t aB = buf + TILESZ + b_row * ROWB;

#pragma unroll
        for (int ks = 0; ks < 4; ++ks) {
            const int ak = (ks * 16 + a_kof) * 2;
            const int bk = (ks * 16 + b_kof) * 2;
            uint32_t bh[4][2];
            {
                uint32_t r[4];
                ldsm_x4(r, aB + bk);
                bh[0][0] = r[0]; bh[0][1] = r[1];
                bh[1][0] = r[2]; bh[1][1] = r[3];
                ldsm_x4(r, aB + 16 * ROWB + bk);
                bh[2][0] = r[0]; bh[2][1] = r[1];
                bh[3][0] = r[2]; bh[3][1] = r[3];
            }
            uint32_t ah[4][4];
#pragma unroll
            for (int mt = 0; mt < 4; ++mt)
                ldsm_x4(ah[mt], aA + mt * 16 * ROWB + ak);
#pragma unroll
            for (int mt = 0; mt < 4; ++mt)
#pragma unroll
                for (int nt = 0; nt < 4; ++nt)
                    mma16816h(acc[mt][nt], ah[mt], bh[nt]);
        }
        if (++st == 3) st = 0;
    }
    __syncthreads();

    const int mbase = by * 128 + wm * 64;
    const int nloc0 = wn * 32;
#pragma unroll
    for (int mt = 0; mt < 4; ++mt) {
#pragma unroll
        for (int half = 0; half < 2; ++half) {
            const int m = mbase + mt * 16 + (lane >> 2) + half * 8;
#pragma unroll
            for (int nt = 0; nt < 4; ++nt) {
                const int nloc = nloc0 + nt * 8 + 2 * (lane & 3);
                const int n = ncol0 + nloc;
                float v0 = acc[mt][nt][half * 2 + 0] + bias_s[nloc];
                float v1 = acc[mt][nt][half * 2 + 1] + bias_s[nloc + 1];
                if (DO_GELU) {
                    v0 = 0.5f * v0 * (1.0f + erff(v0 * 0.70710678118654752f));
                    v1 = 0.5f * v1 * (1.0f + erff(v1 * 0.70710678118654752f));
                }
                if (HAS_RES) {
                    const float2 rv = *(const float2*)(res + (size_t)m * nout + n);
                    v0 += rv.x; v1 += rv.y;
                }
                if (OUTMODE == 0) {
                    *(float2*)(Cf + (size_t)m * nout + n) = make_float2(v0, v1);
                } else {
                    *(__half2*)(chp + (size_t)m * nout + n) = __floats2half2_rn(v0, v1);
                }
            }
        }
    }
}

// ---------------- Flash attention (fp16, causal), double-buffered KV ------------
#define AROWB 144
#define KVSTAGE (128*AROWB)                 // K tile + V tile = 18432
#define ATT_SMEM (128*AROWB + 2*KVSTAGE)    // Q + 2 KV stages = 55296

__global__ void __launch_bounds__(256, 2)
attn_mma(const __half* __restrict__ q, const __half* __restrict__ k,
         const __half* __restrict__ v, __half* __restrict__ o) {
    extern __shared__ char sm[];
    const uint32_t sb = smem_u32(sm);
    const uint32_t sQ = sb;
    const uint32_t sKV = sb + 128 * AROWB;

    const int qt = gridDim.x - 1 - blockIdx.x;   // big tiles first
    const int bh = blockIdx.y;
    const int b = bh >> 4, h = bh & 15;
    const size_t base = (size_t)b * SS * DD + (size_t)h * DHH;
    const int q0 = qt * 128;

    const int tid = threadIdx.x, warp = tid >> 5, lane = tid & 31;

#pragma unroll
    for (int u = 0; u < 4; ++u) {
        const int lin = tid + u * 256;
        const int r = lin >> 3, c = lin & 7;
        cp_async16(sQ + r * AROWB + c * 16, q + base + (size_t)(q0 + r) * DD + c * 8);
    }
    cp_commit();

    {
        const __half* srck = k + base;
        const __half* srcv = v + base;
#pragma unroll
        for (int u = 0; u < 2; ++u) {
            const int lin = tid + u * 256;
            const int rr = lin >> 3, cc = lin & 7;
            const size_t go = (size_t)rr * DD + cc * 8;
            const uint32_t so = rr * AROWB + cc * 16;
            cp_async16(sKV + so, srck + go);
            cp_async16(sKV + 64 * AROWB + so, srcv + go);
        }
        cp_commit();
    }

    float sfr[8][4], oac[8][4];
    float m0 = -1e30f, m1 = -1e30f, l0 = 0.f, l1 = 0.f;
#pragma unroll
    for (int j = 0; j < 8; ++j)
#pragma unroll
        for (int e = 0; e < 4; ++e) oac[j][e] = 0.f;

    const uint32_t qb = sQ + (warp * 16 + (lane & 15)) * AROWB + (((lane >> 4) << 3) << 1);
    const int krow = (lane & 7) + ((lane >> 4) << 3);
    const uint32_t kof = (((lane >> 3) & 1) << 3) << 1;
    const int vrow = lane & 15;
    const uint32_t vof = (((lane >> 4) << 3)) << 1;

    const int ntile = qt * 2 + 2;
    for (int kt = 0; kt < ntile; ++kt) {
        cp_wait<0>();
        __syncthreads();
        if (kt + 1 < ntile) {
            const int k1 = (kt + 1) * 64;
            const uint32_t dst = sKV + ((kt + 1) & 1) * KVSTAGE;
            const __half* srck = k + base + (size_t)k1 * DD;
            const __half* srcv = v + base + (size_t)k1 * DD;
#pragma unroll
            for (int u = 0; u < 2; ++u) {
                const int lin = tid + u * 256;
                const int rr = lin >> 3, cc = lin & 7;
                const size_t go = (size_t)rr * DD + cc * 8;
                const uint32_t so = rr * AROWB + cc * 16;
                cp_async16(dst + so, srck + go);
                cp_async16(dst + 64 * AROWB + so, srcv + go);
            }
            cp_commit();
        }

        const uint32_t sK = sKV + (kt & 1) * KVSTAGE;
        const uint32_t sV = sK + 64 * AROWB;
        const int k0 = kt * 64;

#pragma unroll
        for (int j = 0; j < 8; ++j)
#pragma unroll
            for (int e = 0; e < 4; ++e) sfr[j][e] = 0.f;
#pragma unroll
        for (int t = 0; t < 4; ++t) {
            uint32_t qa[4];
            ldsm_x4(qa, qb + t * 32);
#pragma unroll
            for (int g = 0; g < 4; ++g) {
                uint32_t kb[4];
                ldsm_x4(kb, sK + (g * 16 + krow) * AROWB + t * 32 + kof);
                mma16816h(sfr[2*g],   qa, kb);
                mma16816h(sfr[2*g+1], qa, kb + 2);
            }
        }

        const float cs = 0.1803368801111204f;   // 0.125 * log2(e)
        const int rg0 = q0 + warp * 16 + (lane >> 2);
        if (kt >= 2 * qt) {
#pragma unroll
            for (int j = 0; j < 8; ++j) {
                const int cb = k0 + j * 8 + 2 * (lane & 3);
#pragma unroll
                for (int e = 0; e < 4; ++e) {
                    const int cg = cb + (e & 1);
                    const int rg = rg0 + ((e >> 1) << 3);
                    const float s = sfr[j][e] * cs;
                    sfr[j][e] = (cg > rg) ? -1e30f : s;
                }
            }
        } else {
#pragma unroll
            for (int j = 0; j < 8; ++j)
#pragma unroll
                for (int e = 0; e < 4; ++e) sfr[j][e] *= cs;
        }
        float mx0 = -1e30f, mx1 = -1e30f;
#pragma unroll
        for (int j = 0; j < 8; ++j) {
            mx0 = fmaxf(mx0, fmaxf(sfr[j][0], sfr[j][1]));
            mx1 = fmaxf(mx1, fmaxf(sfr[j][2], sfr[j][3]));
        }
        mx0 = fmaxf(mx0, __shfl_xor_sync(0xffffffffu, mx0, 1));
        mx0 = fmaxf(mx0, __shfl_xor_sync(0xffffffffu, mx0, 2));
        mx1 = fmaxf(mx1, __shfl_xor_sync(0xffffffffu, mx1, 1));
        mx1 = fmaxf(mx1, __shfl_xor_sync(0xffffffffu, mx1, 2));
        mx0 = fmaxf(mx0, m0);
        mx1 = fmaxf(mx1, m1);
        const float al0 = exp2f(m0 - mx0);
        const float al1 = exp2f(m1 - mx1);
        m0 = mx0; m1 = mx1;
        float s0 = 0.f, s1 = 0.f;
#pragma unroll
        for (int j = 0; j < 8; ++j) {
            float p0 = exp2f(sfr[j][0] - mx0);
            float p1 = exp2f(sfr[j][1] - mx0);
            float p2 = exp2f(sfr[j][2] - mx1);
            float p3 = exp2f(sfr[j][3] - mx1);
            sfr[j][0] = p0; sfr[j][1] = p1; sfr[j][2] = p2; sfr[j][3] = p3;
            s0 += p0 + p1; s1 += p2 + p3;
        }
        s0 += __shfl_xor_sync(0xffffffffu, s0, 1);
        s0 += __shfl_xor_sync(0xffffffffu, s0, 2);
        s1 += __shfl_xor_sync(0xffffffffu, s1, 1);
        s1 += __shfl_xor_sync(0xffffffffu, s1, 2);
        l0 = l0 * al0 + s0;
        l1 = l1 * al1 + s1;
#pragma unroll
        for (int j = 0; j < 8; ++j) {
            oac[j][0] *= al0; oac[j][1] *= al0;
            oac[j][2] *= al1; oac[j][3] *= al1;
        }

#pragma unroll
        for (int t = 0; t < 4; ++t) {
            const float* f0 = sfr[2*t];
            const float* f1 = sfr[2*t+1];
            uint32_t pa[4];
            pa[0] = packh(f0[0], f0[1]);
            pa[1] = packh(f0[2], f0[3]);
            pa[2] = packh(f1[0], f1[1]);
            pa[3] = packh(f1[2], f1[3]);
#pragma unroll
            for (int np = 0; np < 4; ++np) {
                uint32_t vb[4];
                ldsm_x4_t(vb, sV + (t * 16 + vrow) * AROWB + np * 32 + vof);
                mma16816h(oac[2*np],   pa, vb);
                mma16816h(oac[2*np+1], pa, vb + 2);
            }
        }
    }

    const float inv0 = 1.f / l0, inv1 = 1.f / l1;
    const int r0g = q0 + warp * 16 + (lane >> 2);
#pragma unroll
    for (int j = 0; j < 8; ++j) {
        const size_t off0 = base + (size_t)r0g * DD + j * 8 + 2 * (lane & 3);
        const size_t off1 = off0 + (size_t)8 * DD;
        *(__half2*)(o + off0) = __floats2half2_rn(oac[j][0] * inv0, oac[j][1] * inv0);
        *(__half2*)(o + off1) = __floats2half2_rn(oac[j][2] * inv1, oac[j][3] * inv1);
    }
}

// ---------------- LayerNorm -> fp16 (standalone, for ln2) -----------------------
__global__ void ln_half_kernel(const float* __restrict__ x,
                               const float* __restrict__ g,
                               const float* __restrict__ b,
                               __half* __restrict__ y) {
    const int row = blockIdx.x;
    const int tid = threadIdx.x;
    const float* xr = x + (size_t)row * DD;

    float v[4];
    float s = 0.f, s2 = 0.f;
#pragma unroll
    for (int i = 0; i < 4; ++i) {
        v[i] = xr[tid + i * 256];
        s += v[i]; s2 += v[i] * v[i];
    }
    for (int off = 16; off > 0; off >>= 1) {
        s  += __shfl_down_sync(0xffffffffu, s,  off);
        s2 += __shfl_down_sync(0xffffffffu, s2, off);
    }
    __shared__ float rs[8], rs2[8];
    if ((tid & 31) == 0) { rs[tid >> 5] = s; rs2[tid >> 5] = s2; }
    __syncthreads();
    if (tid < 8) { s = rs[tid]; s2 = rs2[tid]; } else { s = 0.f; s2 = 0.f; }
    if (tid < 32) {
        for (int off = 4; off > 0; off >>= 1) {
            s  += __shfl_down_sync(0xffffffffu, s,  off);
            s2 += __shfl_down_sync(0xffffffffu, s2, off);
        }
        if (tid == 0) { rs[0] = s; rs2[0] = s2; }
    }
    __syncthreads();
    const float mean = rs[0] * (1.0f / DD);
    const float var  = rs2[0] * (1.0f / DD) - mean * mean;
    const float inv  = rsqrtf(var + 1e-5f);
    __half* yr = y + (size_t)row * DD;
#pragma unroll
    for (int i = 0; i < 4; ++i) {
        const int c = tid + i * 256;
        yr[c] = __float2half_rn((v[i] - mean) * inv * g[c] + b[c]);
    }
}

// ---------------- host launcher -------------------------------------------------
extern "C" void kernel_launch(void* const* d_in, const int* in_sizes, int n_in,
                              void* d_out, int out_size) {
    const float* x     = (const float*)d_in[0];
    const float* ln1_g = (const float*)d_in[1];
    const float* ln1_b = (const float*)d_in[2];
    const float* wq    = (const float*)d_in[3];
    const float* bq    = (const float*)d_in[4];
    const float* wk    = (const float*)d_in[5];
    const float* bk    = (const float*)d_in[6];
    const float* wv    = (const float*)d_in[7];
    const float* bv    = (const float*)d_in[8];
    const float* wo    = (const float*)d_in[9];
    const float* bo    = (const float*)d_in[10];
    const float* ln2_g = (const float*)d_in[11];
    const float* ln2_b = (const float*)d_in[12];
    const float* w1    = (const float*)d_in[13];
    const float* b1    = (const float*)d_in[14];
    const float* w2    = (const float*)d_in[15];
    const float* b2    = (const float*)d_in[16];
    float* out = (float*)d_out;

    __half *ph, *pq, *pk, *pv, *po, *ph2, *pact;
    __half *pwqkv, *pwo, *pw1, *pw2;
    float *padd1;
    cudaGetSymbolAddress((void**)&ph,   g_h);
    cudaGetSymbolAddress((void**)&pq,   g_q);
    cudaGetSymbolAddress((void**)&pk,   g_k);
    cudaGetSymbolAddress((void**)&pv,   g_v);
    cudaGetSymbolAddress((void**)&po,   g_o);
    cudaGetSymbolAddress((void**)&padd1,g_add1);
    cudaGetSymbolAddress((void**)&ph2,  g_h2);
    cudaGetSymbolAddress((void**)&pact, g_act);
    cudaGetSymbolAddress((void**)&pwqkv,g_wqkv);
    cudaGetSymbolAddress((void**)&pwo,  g_wo);
    cudaGetSymbolAddress((void**)&pw1,  g_w1);
    cudaGetSymbolAddress((void**)&pw2,  g_w2);

    cudaFuncSetAttribute(tc_gemm<2,false,false,true >, cudaFuncAttributeMaxDynamicSharedMemorySize, GEMM_SMEM);
    cudaFuncSetAttribute(tc_gemm<0,true, false,false>, cudaFuncAttributeMaxDynamicSharedMemorySize, GEMM_SMEM);
    cudaFuncSetAttribute(tc_gemm<2,false,true ,false>, cudaFuncAttributeMaxDynamicSharedMemorySize, GEMM_SMEM);
    cudaFuncSetAttribute(attn_mma, cudaFuncAttributeMaxDynamicSharedMemorySize, ATT_SMEM);

    dim3 gridD(DD/128, NTOK/128);
    dim3 gridF(FF/128, NTOK/128);

    // #1 fused prologue: ln1 (4096 blocks) + all weight transposes (12288 blocks)
    prologue_kernel<<<NTOK + 12288, 256>>>(x, ln1_g, ln1_b, ph,
                                           wq, wk, wv, wo, w1, w2,
                                           pwqkv, pwo, pw1, pw2);

    // #2 fused QKV GEMM (768 CTAs, SPLIT3 output routing)
    {
        dim3 grid(3*DD/128, NTOK/128);
        tc_gemm<2,false,false,true><<<grid, 256, GEMM_SMEM>>>(
            ph, pwqkv, bq, bk, bv, nullptr,
            nullptr, pq, pk, pv, NTOK, 3*DD, DD);
    }

    // #3 attention
    {
        dim3 grid(SS/128, BB*HH);
        attn_mma<<<grid, 256, ATT_SMEM>>>(pq, pk, pv, po);
    }

    // #4 O-proj + residual: add1 = x + o@wo + bo
    tc_gemm<0,true,false,false><<<gridD, 256, GEMM_SMEM>>>(
        po, pwo, bo, nullptr, nullptr, x,
        padd1, nullptr, nullptr, nullptr, NTOK, DD, DD);

    // #5 ln2
    ln_half_kernel<<<NTOK, 256>>>(padd1, ln2_g, ln2_b, ph2);

    // #6 MLP up + gelu -> fp16
    tc_gemm<2,false,true,false><<<gridF, 256, GEMM_SMEM>>>(
        ph2, pw1, b1, nullptr, nullptr, nullptr,
        nullptr, pact, nullptr, nullptr, NTOK, FF, DD);

    // #7 MLP down + residual -> out
    tc_gemm<0,true,false,false><<<gridD, 256, GEMM_SMEM>>>(
        pact, pw2, b2, nullptr, nullptr, padd1,
        out, nullptr, nullptr, nullptr, NTOK, DD, FF);
}

// round 16
// speedup vs baseline: 1.0819x; 1.0380x over previous
#include <cuda_runtime.h>
#include <cuda_fp16.h>
#include <math.h>
#include <stdint.h>

// Problem dims (fixed)
#define BB 2
#define SS 2048
#define DD 1024
#define HH 16
#define DHH 64
#define FF 4096
#define NTOK (BB*SS)   // 4096

// ---------------- scratch (device globals) -----------------------------------
__device__ __half g_h  [NTOK*DD];
__device__ __half g_q  [NTOK*DD];
__device__ __half g_k  [NTOK*DD];
__device__ __half g_v  [NTOK*DD];
__device__ __half g_o  [NTOK*DD];
__device__ float  g_add1[NTOK*DD];
__device__ __half g_h2 [NTOK*DD];
__device__ __half g_act[NTOK*FF];
__device__ __half g_wqkv[3*DD*DD];     // concatenated [3*DD, DD] row-major ([N,K])
__device__ __half g_wo[DD*DD];
__device__ __half g_w1[DD*FF], g_w2[FF*DD];

// ---------------- helpers ------------------------------------------------------
__device__ __forceinline__ uint32_t smem_u32(const void* p) {
    uint32_t a;
    asm("{ .reg .u64 t; cvta.to.shared.u64 t, %1; cvt.u32.u64 %0, t; }" : "=r"(a) : "l"(p));
    return a;
}
__device__ __forceinline__ void cp_async16(uint32_t dst, const void* src) {
    asm volatile("cp.async.cg.shared.global [%0], [%1], 16;"
                 :: "r"(dst), "l"(src) : "memory");
}
__device__ __forceinline__ void cp_commit() {
    asm volatile("cp.async.commit_group;" ::: "memory");
}
template<int N>
__device__ __forceinline__ void cp_wait() {
    asm volatile("cp.async.wait_group %0;" :: "n"(N) : "memory");
}
__device__ __forceinline__ void ldsm_x4(uint32_t* r, uint32_t addr) {
    asm volatile("ldmatrix.sync.aligned.m8n8.x4.shared.b16 {%0,%1,%2,%3}, [%4];"
                 : "=r"(r[0]), "=r"(r[1]), "=r"(r[2]), "=r"(r[3]) : "r"(addr));
}
__device__ __forceinline__ void ldsm_x4_t(uint32_t* r, uint32_t addr) {
    asm volatile("ldmatrix.sync.aligned.m8n8.x4.trans.shared.b16 {%0,%1,%2,%3}, [%4];"
                 : "=r"(r[0]), "=r"(r[1]), "=r"(r[2]), "=r"(r[3]) : "r"(addr));
}
__device__ __forceinline__ void mma16816h(float* d, const uint32_t* a, const uint32_t* b) {
    asm volatile(
        "mma.sync.aligned.m16n8k16.row.col.f32.f16.f16.f32 "
        "{%0,%1,%2,%3}, {%4,%5,%6,%7}, {%8,%9}, {%0,%1,%2,%3};"
        : "+f"(d[0]), "+f"(d[1]), "+f"(d[2]), "+f"(d[3])
        : "r"(a[0]), "r"(a[1]), "r"(a[2]), "r"(a[3]), "r"(b[0]), "r"(b[1]));
}
__device__ __forceinline__ uint32_t packh(float a, float b) {
    __half2 t = __floats2half2_rn(a, b);
    return *reinterpret_cast<uint32_t*>(&t);
}

// ---------------- fused prologue: ln1 rows + all weight transposes --------------
__global__ void prologue_kernel(const float* __restrict__ x,
                                const float* __restrict__ g,
                                const float* __restrict__ b,
                                __half* __restrict__ y,
                                const float* __restrict__ wq, const float* __restrict__ wk,
                                const float* __restrict__ wv, const float* __restrict__ wo,
                                const float* __restrict__ w1, const float* __restrict__ w2,
                                __half* __restrict__ oqkv, __half* __restrict__ oo,
                                __half* __restrict__ o1, __half* __restrict__ o2) {
    const int tid = threadIdx.x;
    if (blockIdx.x < NTOK) {
        // -------- LayerNorm row --------
        const int row = blockIdx.x;
        const float* xr = x + (size_t)row * DD;
        float v[4];
        float s = 0.f, s2 = 0.f;
#pragma unroll
        for (int i = 0; i < 4; ++i) {
            v[i] = xr[tid + i * 256];
            s += v[i]; s2 += v[i] * v[i];
        }
        for (int off = 16; off > 0; off >>= 1) {
            s  += __shfl_down_sync(0xffffffffu, s,  off);
            s2 += __shfl_down_sync(0xffffffffu, s2, off);
        }
        __shared__ float rs[8], rs2[8];
        if ((tid & 31) == 0) { rs[tid >> 5] = s; rs2[tid >> 5] = s2; }
        __syncthreads();
        if (tid < 8) { s = rs[tid]; s2 = rs2[tid]; } else { s = 0.f; s2 = 0.f; }
        if (tid < 32) {
            for (int off = 4; off > 0; off >>= 1) {
                s  += __shfl_down_sync(0xffffffffu, s,  off);
                s2 += __shfl_down_sync(0xffffffffu, s2, off);
            }
            if (tid == 0) { rs[0] = s; rs2[0] = s2; }
        }
        __syncthreads();
        const float mean = rs[0] * (1.0f / DD);
        const float var  = rs2[0] * (1.0f / DD) - mean * mean;
        const float inv  = rsqrtf(var + 1e-5f);
        __half* yr = y + (size_t)row * DD;
#pragma unroll
        for (int i = 0; i < 4; ++i) {
            const int c = tid + i * 256;
            yr[c] = __float2half_rn((v[i] - mean) * inv * g[c] + b[c]);
        }
        return;
    }

    // -------- weight transpose tile --------
    int id = blockIdx.x - NTOK;
    const float* w; __half* dst; int K, N;
    if (id < 4096) {
        const int sel = id >> 10; id &= 1023;
        K = DD; N = DD;
        w   = (sel == 0) ? wq : (sel == 1) ? wk : (sel == 2) ? wv : wo;
        dst = (sel == 3) ? oo : oqkv + (size_t)sel * DD * DD;
    } else if (id < 8192) {
        id -= 4096; K = DD; N = FF; w = w1; dst = o1;
    } else {
        id -= 8192; K = FF; N = DD; w = w2; dst = o2;
    }
    const int ntx = N >> 5;
    const int bx = id % ntx;
    const int by = id / ntx;

    __shared__ float t[32][33];
    const int tx = tid & 31;
    const int ty = tid >> 5;
#pragma unroll
    for (int i = 0; i < 32; i += 8)
        t[ty + i][tx] = w[(size_t)(by * 32 + ty + i) * N + bx * 32 + tx];
    __syncthreads();
#pragma unroll
    for (int i = 0; i < 32; i += 8) {
        const int n = bx * 32 + ty + i;
        const int k = by * 32 + tx;
        dst[(size_t)n * K + k] = __float2half_rn(t[tx][ty + i]);
    }
}

// ---------------- fp16 GEMM: C[M,N] = A[M,K] @ B^T ([N,K] fp16) -----------------
// Single fp16 x fp16, fp32 accumulate. CTA 128x128, BK=64, 8 warps (2m x 4n),
// warp tile 64x32. 3-stage ring. SPLIT3 routes output thirds to q/k/v buffers.
#define ROWB 144
#define TILESZ (128*ROWB)      // 18432
#define STAGE  (2*TILESZ)      // 36864 (A,B)
#define GEMM_SMEM (3*STAGE + 512)   // 111104

__device__ __forceinline__ void issue_chunk64(const __half* const* tp, int k0,
                                              uint32_t buf, int tid, int K) {
#pragma unroll
    for (int t = 0; t < 2; ++t) {
#pragma unroll
        for (int u = 0; u < 4; ++u) {
            const int lin = tid + u * 256;
            const int r = lin >> 3;
            const int c8 = lin & 7;
            const void* src = tp[t] + (size_t)r * K + k0 + c8 * 8;
            cp_async16(buf + t * TILESZ + r * ROWB + c8 * 16, src);
        }
    }
    cp_commit();
}

template<int OUTMODE /*0=f32, 2=fp16*/, bool HAS_RES, bool DO_GELU, bool SPLIT3>
__global__ void __launch_bounds__(256, 2)
tc_gemm(const __half* __restrict__ A, const __half* __restrict__ B,
        const float* __restrict__ bias, const float* __restrict__ bias1,
        const float* __restrict__ bias2,
        const float* __restrict__ res,
        float* __restrict__ Cf,
        __half* __restrict__ Ch, __half* __restrict__ Ch1, __half* __restrict__ Ch2,
        int M, int N, int K) {
    extern __shared__ char smem[];
    const uint32_t sbase = smem_u32(smem);
    float* bias_s = (float*)(smem + 3 * STAGE);

    const int tid  = threadIdx.x;
    const int wid  = tid >> 5;
    const int lane = tid & 31;
    const int wm = wid >> 2;        // 0..1 (m)
    const int wn = wid & 3;         // 0..3 (n)
    const int bx = blockIdx.x, by = blockIdx.y;

    const float* bp = bias;
    __half* chp = Ch;
    int nout = N;
    int ncol0 = bx * 128;
    if (SPLIT3) {
        const int seg = bx >> 3;
        bp  = (seg == 0) ? bias : (seg == 1) ? bias1 : bias2;
        chp = (seg == 0) ? Ch   : (seg == 1) ? Ch1   : Ch2;
        nout = DD;
        ncol0 = (bx & 7) * 128;
    }
    if (tid < 128) bias_s[tid] = bp[ncol0 + tid];

    const size_t aoff = (size_t)by * 128 * K;
    const size_t boff = (size_t)bx * 128 * K;
    const __half* tp[2] = { A + aoff, B + boff };

    const int nchunk = K >> 6;   // BK=64

    float acc[4][4][4];
#pragma unroll
    for (int mt = 0; mt < 4; ++mt)
#pragma unroll
        for (int nt = 0; nt < 4; ++nt)
#pragma unroll
            for (int e = 0; e < 4; ++e) acc[mt][nt][e] = 0.f;

    const int a_row = wm * 64 + (lane & 15);
    const int a_kof = (lane >> 4) << 3;
    const int b_row = wn * 32 + (lane & 7) + ((lane >> 4) << 3);
    const int b_kof = ((lane >> 3) & 1) << 3;

    issue_chunk64(tp, 0, sbase, tid, K);
    issue_chunk64(tp, 64, sbase + STAGE, tid, K);

    int st = 0;
    for (int i = 0; i < nchunk; ++i) {
        if (i + 1 < nchunk) cp_wait<1>(); else cp_wait<0>();
        __syncthreads();
        if (i + 2 < nchunk) {
            int st2 = st + 2; if (st2 >= 3) st2 -= 3;
            issue_chunk64(tp, (i + 2) << 6, sbase + st2 * STAGE, tid, K);
        }

        const uint32_t buf = sbase + st * STAGE;
        const uint32_t aA = buf + a_row * ROWB;
        const uint32_t aB = buf + TILESZ + b_row * ROWB;

#pragma unroll
        for (int ks = 0; ks < 4; ++ks) {
            const int ak = (ks * 16 + a_kof) * 2;
            const int bk = (ks * 16 + b_kof) * 2;
            uint32_t bh[4][2];
            {
                uint32_t r[4];
                ldsm_x4(r, aB + bk);
                bh[0][0] = r[0]; bh[0][1] = r[1];
                bh[1][0] = r[2]; bh[1][1] = r[3];
                ldsm_x4(r, aB + 16 * ROWB + bk);
                bh[2][0] = r[0]; bh[2][1] = r[1];
                bh[3][0] = r[2]; bh[3][1] = r[3];
            }
            uint32_t ah[4][4];
#pragma unroll
            for (int mt = 0; mt < 4; ++mt)
                ldsm_x4(ah[mt], aA + mt * 16 * ROWB + ak);
#pragma unroll
            for (int mt = 0; mt < 4; ++mt)
#pragma unroll
                for (int nt = 0; nt < 4; ++nt)
                    mma16816h(acc[mt][nt], ah[mt], bh[nt]);
        }
        if (++st == 3) st = 0;
    }
    __syncthreads();

    const int mbase = by * 128 + wm * 64;
    const int nloc0 = wn * 32;
#pragma unroll
    for (int mt = 0; mt < 4; ++mt) {
#pragma unroll
        for (int half = 0; half < 2; ++half) {
            const int m = mbase + mt * 16 + (lane >> 2) + half * 8;
#pragma unroll
            for (int nt = 0; nt < 4; ++nt) {
                const int nloc = nloc0 + nt * 8 + 2 * (lane & 3);
                const int n = ncol0 + nloc;
                float v0 = acc[mt][nt][half * 2 + 0] + bias_s[nloc];
                float v1 = acc[mt][nt][half * 2 + 1] + bias_s[nloc + 1];
                if (DO_GELU) {
                    v0 = 0.5f * v0 * (1.0f + erff(v0 * 0.70710678118654752f));
                    v1 = 0.5f * v1 * (1.0f + erff(v1 * 0.70710678118654752f));
                }
                if (HAS_RES) {
                    const float2 rv = *(const float2*)(res + (size_t)m * nout + n);
                    v0 += rv.x; v1 += rv.y;
                }
                if (OUTMODE == 0) {
                    *(float2*)(Cf + (size_t)m * nout + n) = make_float2(v0, v1);
                } else {
                    *(__half2*)(chp + (size_t)m * nout + n) = __floats2half2_rn(v0, v1);
                }
            }
        }
    }
}

// ---------------- Flash attention (fp16, causal), double-buffered KV ------------
// Paired q-tiles per CTA for wave balance: CTA bx handles qt=bx and qt=15-bx
// (work (bx+1)+(16-bx) = 17 tile-units for every CTA -> one balanced wave).
#define AROWB 144
#define KVSTAGE (128*AROWB)                 // K tile + V tile = 18432
#define ATT_SMEM (128*AROWB + 2*KVSTAGE)    // Q + 2 KV stages = 55296

__global__ void __launch_bounds__(256, 2)
attn_mma(const __half* __restrict__ q, const __half* __restrict__ k,
         const __half* __restrict__ v, __half* __restrict__ o) {
    extern __shared__ char sm[];
    const uint32_t sb = smem_u32(sm);
    const uint32_t sQ = sb;
    const uint32_t sKV = sb + 128 * AROWB;

    const int bh = blockIdx.y;
    const int b = bh >> 4, h = bh & 15;
    const size_t base = (size_t)b * SS * DD + (size_t)h * DHH;

    const int tid = threadIdx.x, warp = tid >> 5, lane = tid & 31;
    const int nqt = gridDim.x * 2;    // 16

    const uint32_t qb = sQ + (warp * 16 + (lane & 15)) * AROWB + (((lane >> 4) << 3) << 1);
    const int krow = (lane & 7) + ((lane >> 4) << 3);
    const uint32_t kof = (((lane >> 3) & 1) << 3) << 1;
    const int vrow = lane & 15;
    const uint32_t vof = (((lane >> 4) << 3)) << 1;

#pragma unroll
    for (int part = 0; part < 2; ++part) {
        const int qt = (part == 0) ? ((int)gridDim.x - 1 - blockIdx.x)        // big first
                                   : (nqt - 1 - ((int)gridDim.x - 1 - blockIdx.x));
        const int q0 = qt * 128;

        if (part == 1) __syncthreads();   // prior sub-tile's KV reads complete

        // stage Q (group 0)
#pragma unroll
        for (int u = 0; u < 4; ++u) {
            const int lin = tid + u * 256;
            const int r = lin >> 3, c = lin & 7;
            cp_async16(sQ + r * AROWB + c * 16, q + base + (size_t)(q0 + r) * DD + c * 8);
        }
        cp_commit();

        // issue kv tile 0 (group 1)
        {
            const __half* srck = k + base;
            const __half* srcv = v + base;
#pragma unroll
            for (int u = 0; u < 2; ++u) {
                const int lin = tid + u * 256;
                const int rr = lin >> 3, cc = lin & 7;
                const size_t go = (size_t)rr * DD + cc * 8;
                const uint32_t so = rr * AROWB + cc * 16;
                cp_async16(sKV + so, srck + go);
                cp_async16(sKV + 64 * AROWB + so, srcv + go);
            }
            cp_commit();
        }

        float sfr[8][4], oac[8][4];
        float m0 = -1e30f, m1 = -1e30f, l0 = 0.f, l1 = 0.f;
#pragma unroll
        for (int j = 0; j < 8; ++j)
#pragma unroll
            for (int e = 0; e < 4; ++e) oac[j][e] = 0.f;

        const int ntile = qt * 2 + 2;
        for (int kt = 0; kt < ntile; ++kt) {
            cp_wait<0>();
            __syncthreads();
            if (kt + 1 < ntile) {
                const int k1 = (kt + 1) * 64;
                const uint32_t dst = sKV + ((kt + 1) & 1) * KVSTAGE;
                const __half* srck = k + base + (size_t)k1 * DD;
                const __half* srcv = v + base + (size_t)k1 * DD;
#pragma unroll
                for (int u = 0; u < 2; ++u) {
                    const int lin = tid + u * 256;
                    const int rr = lin >> 3, cc = lin & 7;
                    const size_t go = (size_t)rr * DD + cc * 8;
                    const uint32_t so = rr * AROWB + cc * 16;
                    cp_async16(dst + so, srck + go);
                    cp_async16(dst + 64 * AROWB + so, srcv + go);
                }
                cp_commit();
            }

            const uint32_t sK = sKV + (kt & 1) * KVSTAGE;
            const uint32_t sV = sK + 64 * AROWB;
            const int k0 = kt * 64;

            // ---- scores S = Q @ K^T ----
#pragma unroll
            for (int j = 0; j < 8; ++j)
#pragma unroll
                for (int e = 0; e < 4; ++e) sfr[j][e] = 0.f;
#pragma unroll
            for (int t = 0; t < 4; ++t) {
                uint32_t qa[4];
                ldsm_x4(qa, qb + t * 32);
#pragma unroll
                for (int g = 0; g < 4; ++g) {
                    uint32_t kb[4];
                    ldsm_x4(kb, sK + (g * 16 + krow) * AROWB + t * 32 + kof);
                    mma16816h(sfr[2*g],   qa, kb);
                    mma16816h(sfr[2*g+1], qa, kb + 2);
                }
            }

            // ---- online softmax (base-2 domain, warp-local rows) ----
            const float cs = 0.1803368801111204f;   // 0.125 * log2(e)
            const int rg0 = q0 + warp * 16 + (lane >> 2);
            if (kt >= 2 * qt) {
#pragma unroll
                for (int j = 0; j < 8; ++j) {
                    const int cb = k0 + j * 8 + 2 * (lane & 3);
#pragma unroll
                    for (int e = 0; e < 4; ++e) {
                        const int cg = cb + (e & 1);
                        const int rg = rg0 + ((e >> 1) << 3);
                        const float s = sfr[j][e] * cs;
                        sfr[j][e] = (cg > rg) ? -1e30f : s;
                    }
                }
            } else {
#pragma unroll
                for (int j = 0; j < 8; ++j)
#pragma unroll
                    for (int e = 0; e < 4; ++e) sfr[j][e] *= cs;
            }
            float mx0 = -1e30f, mx1 = -1e30f;
#pragma unroll
            for (int j = 0; j < 8; ++j) {
                mx0 = fmaxf(mx0, fmaxf(sfr[j][0], sfr[j][1]));
                mx1 = fmaxf(mx1, fmaxf(sfr[j][2], sfr[j][3]));
            }
            mx0 = fmaxf(mx0, __shfl_xor_sync(0xffffffffu, mx0, 1));
            mx0 = fmaxf(mx0, __shfl_xor_sync(0xffffffffu, mx0, 2));
            mx1 = fmaxf(mx1, __shfl_xor_sync(0xffffffffu, mx1, 1));
            mx1 = fmaxf(mx1, __shfl_xor_sync(0xffffffffu, mx1, 2));
            mx0 = fmaxf(mx0, m0);
            mx1 = fmaxf(mx1, m1);
            const float al0 = exp2f(m0 - mx0);
            const float al1 = exp2f(m1 - mx1);
            m0 = mx0; m1 = mx1;
            float s0 = 0.f, s1 = 0.f;
#pragma unroll
            for (int j = 0; j < 8; ++j) {
                float p0 = exp2f(sfr[j][0] - mx0);
                float p1 = exp2f(sfr[j][1] - mx0);
                float p2 = exp2f(sfr[j][2] - mx1);
                float p3 = exp2f(sfr[j][3] - mx1);
                sfr[j][0] = p0; sfr[j][1] = p1; sfr[j][2] = p2; sfr[j][3] = p3;
                s0 += p0 + p1; s1 += p2 + p3;
            }
            s0 += __shfl_xor_sync(0xffffffffu, s0, 1);
            s0 += __shfl_xor_sync(0xffffffffu, s0, 2);
            s1 += __shfl_xor_sync(0xffffffffu, s1, 1);
            s1 += __shfl_xor_sync(0xffffffffu, s1, 2);
            l0 = l0 * al0 + s0;
            l1 = l1 * al1 + s1;
#pragma unroll
            for (int j = 0; j < 8; ++j) {
                oac[j][0] *= al0; oac[j][1] *= al0;
                oac[j][2] *= al1; oac[j][3] *= al1;
            }

            // ---- O += P @ V ----
#pragma unroll
            for (int t = 0; t < 4; ++t) {
                const float* f0 = sfr[2*t];
                const float* f1 = sfr[2*t+1];
                uint32_t pa[4];
                pa[0] = packh(f0[0], f0[1]);
                pa[1] = packh(f0[2], f0[3]);
                pa[2] = packh(f1[0], f1[1]);
                pa[3] = packh(f1[2], f1[3]);
#pragma unroll
                for (int np = 0; np < 4; ++np) {
                    uint32_t vb[4];
                    ldsm_x4_t(vb, sV + (t * 16 + vrow) * AROWB + np * 32 + vof);
                    mma16816h(oac[2*np],   pa, vb);
                    mma16816h(oac[2*np+1], pa, vb + 2);
                }
            }
        }

        // ---- write O (fp16) ----
        const float inv0 = 1.f / l0, inv1 = 1.f / l1;
        const int r0g = q0 + warp * 16 + (lane >> 2);
#pragma unroll
        for (int j = 0; j < 8; ++j) {
            const size_t off0 = base + (size_t)r0g * DD + j * 8 + 2 * (lane & 3);
            const size_t off1 = off0 + (size_t)8 * DD;
            *(__half2*)(o + off0) = __floats2half2_rn(oac[j][0] * inv0, oac[j][1] * inv0);
            *(__half2*)(o + off1) = __floats2half2_rn(oac[j][2] * inv1, oac[j][3] * inv1);
        }
    }
}

// ---------------- LayerNorm -> fp16 (standalone, for ln2) -----------------------
__global__ void ln_half_kernel(const float* __restrict__ x,
                               const float* __restrict__ g,
                               const float* __restrict__ b,
                               __half* __restrict__ y) {
    const int row = blockIdx.x;
    const int tid = threadIdx.x;
    const float* xr = x + (size_t)row * DD;

    float v[4];
    float s = 0.f, s2 = 0.f;
#pragma unroll
    for (int i = 0; i < 4; ++i) {
        v[i] = xr[tid + i * 256];
        s += v[i]; s2 += v[i] * v[i];
    }
    for (int off = 16; off > 0; off >>= 1) {
        s  += __shfl_down_sync(0xffffffffu, s,  off);
        s2 += __shfl_down_sync(0xffffffffu, s2, off);
    }
    __shared__ float rs[8], rs2[8];
    if ((tid & 31) == 0) { rs[tid >> 5] = s; rs2[tid >> 5] = s2; }
    __syncthreads();
    if (tid < 8) { s = rs[tid]; s2 = rs2[tid]; } else { s = 0.f; s2 = 0.f; }
    if (tid < 32) {
        for (int off = 4; off > 0; off >>= 1) {
            s  += __shfl_down_sync(0xffffffffu, s,  off);
            s2 += __shfl_down_sync(0xffffffffu, s2, off);
        }
        if (tid == 0) { rs[0] = s; rs2[0] = s2; }
    }
    __syncthreads();
    const float mean = rs[0] * (1.0f / DD);
    const float var  = rs2[0] * (1.0f / DD) - mean * mean;
    const float inv  = rsqrtf(var + 1e-5f);
    __half* yr = y + (size_t)row * DD;
#pragma unroll
    for (int i = 0; i < 4; ++i) {
        const int c = tid + i * 256;
        yr[c] = __float2half_rn((v[i] - mean) * inv * g[c] + b[c]);
    }
}

// ---------------- host launcher -------------------------------------------------
extern "C" void kernel_launch(void* const* d_in, const int* in_sizes, int n_in,
                              void* d_out, int out_size) {
    const float* x     = (const float*)d_in[0];
    const float* ln1_g = (const float*)d_in[1];
    const float* ln1_b = (const float*)d_in[2];
    const float* wq    = (const float*)d_in[3];
    const float* bq    = (const float*)d_in[4];
    const float* wk    = (const float*)d_in[5];
    const float* bk    = (const float*)d_in[6];
    const float* wv    = (const float*)d_in[7];
    const float* bv    = (const float*)d_in[8];
    const float* wo    = (const float*)d_in[9];
    const float* bo    = (const float*)d_in[10];
    const float* ln2_g = (const float*)d_in[11];
    const float* ln2_b = (const float*)d_in[12];
    const float* w1    = (const float*)d_in[13];
    const float* b1    = (const float*)d_in[14];
    const float* w2    = (const float*)d_in[15];
    const float* b2    = (const float*)d_in[16];
    float* out = (float*)d_out;

    __half *ph, *pq, *pk, *pv, *po, *ph2, *pact;
    __half *pwqkv, *pwo, *pw1, *pw2;
    float *padd1;
    cudaGetSymbolAddress((void**)&ph,   g_h);
    cudaGetSymbolAddress((void**)&pq,   g_q);
    cudaGetSymbolAddress((void**)&pk,   g_k);
    cudaGetSymbolAddress((void**)&pv,   g_v);
    cudaGetSymbolAddress((void**)&po,   g_o);
    cudaGetSymbolAddress((void**)&padd1,g_add1);
    cudaGetSymbolAddress((void**)&ph2,  g_h2);
    cudaGetSymbolAddress((void**)&pact, g_act);
    cudaGetSymbolAddress((void**)&pwqkv,g_wqkv);
    cudaGetSymbolAddress((void**)&pwo,  g_wo);
    cudaGetSymbolAddress((void**)&pw1,  g_w1);
    cudaGetSymbolAddress((void**)&pw2,  g_w2);

    cudaFuncSetAttribute(tc_gemm<2,false,false,true >, cudaFuncAttributeMaxDynamicSharedMemorySize, GEMM_SMEM);
    cudaFuncSetAttribute(tc_gemm<0,true, false,false>, cudaFuncAttributeMaxDynamicSharedMemorySize, GEMM_SMEM);
    cudaFuncSetAttribute(tc_gemm<2,false,true ,false>, cudaFuncAttributeMaxDynamicSharedMemorySize, GEMM_SMEM);
    cudaFuncSetAttribute(attn_mma, cudaFuncAttributeMaxDynamicSharedMemorySize, ATT_SMEM);

    dim3 gridD(DD/128, NTOK/128);
    dim3 gridF(FF/128, NTOK/128);

    // #1 fused prologue: ln1 (4096 blocks) + all weight transposes (12288 blocks)
    prologue_kernel<<<NTOK + 12288, 256>>>(x, ln1_g, ln1_b, ph,
                                           wq, wk, wv, wo, w1, w2,
                                           pwqkv, pwo, pw1, pw2);

    // #2 fused QKV GEMM (768 CTAs, SPLIT3 output routing)
    {
        dim3 grid(3*DD/128, NTOK/128);
        tc_gemm<2,false,false,true><<<grid, 256, GEMM_SMEM>>>(
            ph, pwqkv, bq, bk, bv, nullptr,
            nullptr, pq, pk, pv, NTOK, 3*DD, DD);
    }

    // #3 attention (paired q-tiles: perfectly balanced single wave)
    {
        dim3 grid(SS/256, BB*HH);   // 8 x 32 = 256 CTAs
        attn_mma<<<grid, 256, ATT_SMEM>>>(pq, pk, pv, po);
    }

    // #4 O-proj + residual: add1 = x + o@wo + bo
    tc_gemm<0,true,false,false><<<gridD, 256, GEMM_SMEM>>>(
        po, pwo, bo, nullptr, nullptr, x,
        padd1, nullptr, nullptr, nullptr, NTOK, DD, DD);

    // #5 ln2
    ln_half_kernel<<<NTOK, 256>>>(padd1, ln2_g, ln2_b, ph2);

    // #6 MLP up + gelu -> fp16
    tc_gemm<2,false,true,false><<<gridF, 256, GEMM_SMEM>>>(
        ph2, pw1, b1, nullptr, nullptr, nullptr,
        nullptr, pact, nullptr, nullptr, NTOK, FF, DD);

    // #7 MLP down + residual -> out
    tc_gemm<0,true,false,false><<<gridD, 256, GEMM_SMEM>>>(
        pact, pw2, b2, nullptr, nullptr, padd1,
        out, nullptr, nullptr, nullptr, NTOK, DD, FF);
}

// round 17
// speedup vs baseline: 1.0901x; 1.0075x over previous
#include <cuda_runtime.h>
#include <cuda_fp16.h>
#include <math.h>
#include <stdint.h>

// Problem dims (fixed)
#define BB 2
#define SS 2048
#define DD 1024
#define HH 16
#define DHH 64
#define FF 4096
#define NTOK (BB*SS)   // 4096

// ---------------- scratch (device globals) -----------------------------------
__device__ __half g_h  [NTOK*DD];
__device__ __half g_q  [NTOK*DD];
__device__ __half g_k  [NTOK*DD];
__device__ __half g_v  [NTOK*DD];
__device__ __half g_o  [NTOK*DD];
__device__ float  g_add1[NTOK*DD];
__device__ __half g_h2 [NTOK*DD];
__device__ __half g_act[NTOK*FF];
__device__ __half g_wqkv[3*DD*DD];     // concatenated [3*DD, DD] row-major ([N,K])
__device__ __half g_wo[DD*DD];
__device__ __half g_w1[DD*FF], g_w2[FF*DD];

// ---------------- helpers ------------------------------------------------------
__device__ __forceinline__ uint32_t smem_u32(const void* p) {
    uint32_t a;
    asm("{ .reg .u64 t; cvta.to.shared.u64 t, %1; cvt.u32.u64 %0, t; }" : "=r"(a) : "l"(p));
    return a;
}
__device__ __forceinline__ void cp_async16(uint32_t dst, const void* src) {
    asm volatile("cp.async.cg.shared.global [%0], [%1], 16;"
                 :: "r"(dst), "l"(src) : "memory");
}
__device__ __forceinline__ void cp_commit() {
    asm volatile("cp.async.commit_group;" ::: "memory");
}
template<int N>
__device__ __forceinline__ void cp_wait() {
    asm volatile("cp.async.wait_group %0;" :: "n"(N) : "memory");
}
__device__ __forceinline__ void ldsm_x4(uint32_t* r, uint32_t addr) {
    asm volatile("ldmatrix.sync.aligned.m8n8.x4.shared.b16 {%0,%1,%2,%3}, [%4];"
                 : "=r"(r[0]), "=r"(r[1]), "=r"(r[2]), "=r"(r[3]) : "r"(addr));
}
__device__ __forceinline__ void ldsm_x4_t(uint32_t* r, uint32_t addr) {
    asm volatile("ldmatrix.sync.aligned.m8n8.x4.trans.shared.b16 {%0,%1,%2,%3}, [%4];"
                 : "=r"(r[0]), "=r"(r[1]), "=r"(r[2]), "=r"(r[3]) : "r"(addr));
}
__device__ __forceinline__ void mma16816h(float* d, const uint32_t* a, const uint32_t* b) {
    asm volatile(
        "mma.sync.aligned.m16n8k16.row.col.f32.f16.f16.f32 "
        "{%0,%1,%2,%3}, {%4,%5,%6,%7}, {%8,%9}, {%0,%1,%2,%3};"
        : "+f"(d[0]), "+f"(d[1]), "+f"(d[2]), "+f"(d[3])
        : "r"(a[0]), "r"(a[1]), "r"(a[2]), "r"(a[3]), "r"(b[0]), "r"(b[1]));
}
__device__ __forceinline__ uint32_t packh(float a, float b) {
    __half2 t = __floats2half2_rn(a, b);
    return *reinterpret_cast<uint32_t*>(&t);
}

// ---------------- fused prologue: ln1 rows + all weight transposes --------------
__global__ void prologue_kernel(const float* __restrict__ x,
                                const float* __restrict__ g,
                                const float* __restrict__ b,
                                __half* __restrict__ y,
                                const float* __restrict__ wq, const float* __restrict__ wk,
                                const float* __restrict__ wv, const float* __restrict__ wo,
                                const float* __restrict__ w1, const float* __restrict__ w2,
                                __half* __restrict__ oqkv, __half* __restrict__ oo,
                                __half* __restrict__ o1, __half* __restrict__ o2) {
    const int tid = threadIdx.x;
    if (blockIdx.x < NTOK) {
        // -------- LayerNorm row --------
        const int row = blockIdx.x;
        const float* xr = x + (size_t)row * DD;
        float v[4];
        float s = 0.f, s2 = 0.f;
#pragma unroll
        for (int i = 0; i < 4; ++i) {
            v[i] = xr[tid + i * 256];
            s += v[i]; s2 += v[i] * v[i];
        }
        for (int off = 16; off > 0; off >>= 1) {
            s  += __shfl_down_sync(0xffffffffu, s,  off);
            s2 += __shfl_down_sync(0xffffffffu, s2, off);
        }
        __shared__ float rs[8], rs2[8];
        if ((tid & 31) == 0) { rs[tid >> 5] = s; rs2[tid >> 5] = s2; }
        __syncthreads();
        if (tid < 8) { s = rs[tid]; s2 = rs2[tid]; } else { s = 0.f; s2 = 0.f; }
        if (tid < 32) {
            for (int off = 4; off > 0; off >>= 1) {
                s  += __shfl_down_sync(0xffffffffu, s,  off);
                s2 += __shfl_down_sync(0xffffffffu, s2, off);
            }
            if (tid == 0) { rs[0] = s; rs2[0] = s2; }
        }
        __syncthreads();
        const float mean = rs[0] * (1.0f / DD);
        const float var  = rs2[0] * (1.0f / DD) - mean * mean;
        const float inv  = rsqrtf(var + 1e-5f);
        __half* yr = y + (size_t)row * DD;
#pragma unroll
        for (int i = 0; i < 4; ++i) {
            const int c = tid + i * 256;
            yr[c] = __float2half_rn((v[i] - mean) * inv * g[c] + b[c]);
        }
        return;
    }

    // -------- weight transpose tile --------
    int id = blockIdx.x - NTOK;
    const float* w; __half* dst; int K, N;
    if (id < 4096) {
        const int sel = id >> 10; id &= 1023;
        K = DD; N = DD;
        w   = (sel == 0) ? wq : (sel == 1) ? wk : (sel == 2) ? wv : wo;
        dst = (sel == 3) ? oo : oqkv + (size_t)sel * DD * DD;
    } else if (id < 8192) {
        id -= 4096; K = DD; N = FF; w = w1; dst = o1;
    } else {
        id -= 8192; K = FF; N = DD; w = w2; dst = o2;
    }
    const int ntx = N >> 5;
    const int bx = id % ntx;
    const int by = id / ntx;

    __shared__ float t[32][33];
    const int tx = tid & 31;
    const int ty = tid >> 5;
#pragma unroll
    for (int i = 0; i < 32; i += 8)
        t[ty + i][tx] = w[(size_t)(by * 32 + ty + i) * N + bx * 32 + tx];
    __syncthreads();
#pragma unroll
    for (int i = 0; i < 32; i += 8) {
        const int n = bx * 32 + ty + i;
        const int k = by * 32 + tx;
        dst[(size_t)n * K + k] = __float2half_rn(t[tx][ty + i]);
    }
}

// ---------------- fp16 GEMM: C[M,N] = A[M,K] @ B^T ([N,K] fp16) -----------------
// Single fp16 x fp16, fp32 accumulate. CTA 128x128, BK=64, 8 warps (2m x 4n),
// warp tile 64x32. 3-stage ring. SPLIT3 routes output thirds to q/k/v buffers.
#define ROWB 144
#define TILESZ (128*ROWB)      // 18432
#define STAGE  (2*TILESZ)      // 36864 (A,B)
#define GEMM_SMEM (3*STAGE + 512)   // 111104

__device__ __forceinline__ void issue_chunk64(const __half* const* tp, int k0,
                                              uint32_t buf, int tid, int K) {
#pragma unroll
    for (int t = 0; t < 2; ++t) {
#pragma unroll
        for (int u = 0; u < 4; ++u) {
            const int lin = tid + u * 256;
            const int r = lin >> 3;
            const int c8 = lin & 7;
            const void* src = tp[t] + (size_t)r * K + k0 + c8 * 8;
            cp_async16(buf + t * TILESZ + r * ROWB + c8 * 16, src);
        }
    }
    cp_commit();
}

template<int OUTMODE /*0=f32, 2=fp16*/, bool HAS_RES, bool DO_GELU, bool SPLIT3>
__global__ void __launch_bounds__(256, 2)
tc_gemm(const __half* __restrict__ A, const __half* __restrict__ B,
        const float* __restrict__ bias, const float* __restrict__ bias1,
        const float* __restrict__ bias2,
        const float* __restrict__ res,
        float* __restrict__ Cf,
        __half* __restrict__ Ch, __half* __restrict__ Ch1, __half* __restrict__ Ch2,
        int M, int N, int K) {
    extern __shared__ char smem[];
    const uint32_t sbase = smem_u32(smem);
    float* bias_s = (float*)(smem + 3 * STAGE);

    const int tid  = threadIdx.x;
    const int wid  = tid >> 5;
    const int lane = tid & 31;
    const int wm = wid >> 2;        // 0..1 (m)
    const int wn = wid & 3;         // 0..3 (n)
    const int bx = blockIdx.x, by = blockIdx.y;

    const float* bp = bias;
    __half* chp = Ch;
    int nout = N;
    int ncol0 = bx * 128;
    if (SPLIT3) {
        const int seg = bx >> 3;
        bp  = (seg == 0) ? bias : (seg == 1) ? bias1 : bias2;
        chp = (seg == 0) ? Ch   : (seg == 1) ? Ch1   : Ch2;
        nout = DD;
        ncol0 = (bx & 7) * 128;
    }
    if (tid < 128) bias_s[tid] = bp[ncol0 + tid];

    const size_t aoff = (size_t)by * 128 * K;
    const size_t boff = (size_t)bx * 128 * K;
    const __half* tp[2] = { A + aoff, B + boff };

    const int nchunk = K >> 6;   // BK=64

    float acc[4][4][4];
#pragma unroll
    for (int mt = 0; mt < 4; ++mt)
#pragma unroll
        for (int nt = 0; nt < 4; ++nt)
#pragma unroll
            for (int e = 0; e < 4; ++e) acc[mt][nt][e] = 0.f;

    const int a_row = wm * 64 + (lane & 15);
    const int a_kof = (lane >> 4) << 3;
    const int b_row = wn * 32 + (lane & 7) + ((lane >> 4) << 3);
    const int b_kof = ((lane >> 3) & 1) << 3;

    issue_chunk64(tp, 0, sbase, tid, K);
    issue_chunk64(tp, 64, sbase + STAGE, tid, K);

    int st = 0;
    for (int i = 0; i < nchunk; ++i) {
        if (i + 1 < nchunk) cp_wait<1>(); else cp_wait<0>();
        __syncthreads();
        if (i + 2 < nchunk) {
            int st2 = st + 2; if (st2 >= 3) st2 -= 3;
            issue_chunk64(tp, (i + 2) << 6, sbase + st2 * STAGE, tid, K);
        }

        const uint32_t buf = sbase + st * STAGE;
        const uint32_t aA = buf + a_row * ROWB;
        const uint32_t aB = buf + TILESZ + b_row * ROWB;

#pragma unroll
        for (int ks = 0; ks < 4; ++ks) {
            const int ak = (ks * 16 + a_kof) * 2;
            const int bk = (ks * 16 + b_kof) * 2;
            uint32_t bh[4][2];
            {
                uint32_t r[4];
                ldsm_x4(r, aB + bk);
                bh[0][0] = r[0]; bh[0][1] = r[1];
                bh[1][0] = r[2]; bh[1][1] = r[3];
                ldsm_x4(r, aB + 16 * ROWB + bk);
                bh[2][0] = r[0]; bh[2][1] = r[1];
                bh[3][0] = r[2]; bh[3][1] = r[3];
            }
            uint32_t ah[4][4];
#pragma unroll
            for (int mt = 0; mt < 4; ++mt)
                ldsm_x4(ah[mt], aA + mt * 16 * ROWB + ak);
#pragma unroll
            for (int mt = 0; mt < 4; ++mt)
#pragma unroll
                for (int nt = 0; nt < 4; ++nt)
                    mma16816h(acc[mt][nt], ah[mt], bh[nt]);
        }
        if (++st == 3) st = 0;
    }
    // no barrier needed: epilogue reads only registers and bias_s (outside the
    // staging ring, written pre-loop and synchronized by the first loop barrier).

    const int mbase = by * 128 + wm * 64;
    const int nloc0 = wn * 32;
#pragma unroll
    for (int mt = 0; mt < 4; ++mt) {
#pragma unroll
        for (int half = 0; half < 2; ++half) {
            const int m = mbase + mt * 16 + (lane >> 2) + half * 8;
#pragma unroll
            for (int nt = 0; nt < 4; ++nt) {
                const int nloc = nloc0 + nt * 8 + 2 * (lane & 3);
                const int n = ncol0 + nloc;
                float v0 = acc[mt][nt][half * 2 + 0] + bias_s[nloc];
                float v1 = acc[mt][nt][half * 2 + 1] + bias_s[nloc + 1];
                if (DO_GELU) {
                    v0 = 0.5f * v0 * (1.0f + erff(v0 * 0.70710678118654752f));
                    v1 = 0.5f * v1 * (1.0f + erff(v1 * 0.70710678118654752f));
                }
                if (HAS_RES) {
                    const float2 rv = *(const float2*)(res + (size_t)m * nout + n);
                    v0 += rv.x; v1 += rv.y;
                }
                if (OUTMODE == 0) {
                    *(float2*)(Cf + (size_t)m * nout + n) = make_float2(v0, v1);
                } else {
                    *(__half2*)(chp + (size_t)m * nout + n) = __floats2half2_rn(v0, v1);
                }
            }
        }
    }
}

// ---------------- Flash attention (fp16, causal), double-buffered KV ------------
// Paired q-tiles per CTA for wave balance: CTA bx handles qt=bx and qt=15-bx
// (work (bx+1)+(16-bx) = 17 tile-units for every CTA -> one balanced wave).
#define AROWB 144
#define KVSTAGE (128*AROWB)                 // K tile + V tile = 18432
#define ATT_SMEM (128*AROWB + 2*KVSTAGE)    // Q + 2 KV stages = 55296

__global__ void __launch_bounds__(256, 2)
attn_mma(const __half* __restrict__ q, const __half* __restrict__ k,
         const __half* __restrict__ v, __half* __restrict__ o) {
    extern __shared__ char sm[];
    const uint32_t sb = smem_u32(sm);
    const uint32_t sQ = sb;
    const uint32_t sKV = sb + 128 * AROWB;

    const int bh = blockIdx.y;
    const int b = bh >> 4, h = bh & 15;
    const size_t base = (size_t)b * SS * DD + (size_t)h * DHH;

    const int tid = threadIdx.x, warp = tid >> 5, lane = tid & 31;
    const int nqt = gridDim.x * 2;    // 16

    const uint32_t qb = sQ + (warp * 16 + (lane & 15)) * AROWB + (((lane >> 4) << 3) << 1);
    const int krow = (lane & 7) + ((lane >> 4) << 3);
    const uint32_t kof = (((lane >> 3) & 1) << 3) << 1;
    const int vrow = lane & 15;
    const uint32_t vof = (((lane >> 4) << 3)) << 1;

#pragma unroll
    for (int part = 0; part < 2; ++part) {
        const int qt = (part == 0) ? ((int)gridDim.x - 1 - blockIdx.x)        // big first
                                   : (nqt - 1 - ((int)gridDim.x - 1 - blockIdx.x));
        const int q0 = qt * 128;

        if (part == 1) __syncthreads();   // prior sub-tile's KV reads complete

        // stage Q (group 0)
#pragma unroll
        for (int u = 0; u < 4; ++u) {
            const int lin = tid + u * 256;
            const int r = lin >> 3, c = lin & 7;
            cp_async16(sQ + r * AROWB + c * 16, q + base + (size_t)(q0 + r) * DD + c * 8);
        }
        cp_commit();

        // issue kv tile 0 (group 1)
        {
            const __half* srck = k + base;
            const __half* srcv = v + base;
#pragma unroll
            for (int u = 0; u < 2; ++u) {
                const int lin = tid + u * 256;
                const int rr = lin >> 3, cc = lin & 7;
                const size_t go = (size_t)rr * DD + cc * 8;
                const uint32_t so = rr * AROWB + cc * 16;
                cp_async16(sKV + so, srck + go);
                cp_async16(sKV + 64 * AROWB + so, srcv + go);
            }
            cp_commit();
        }

        float sfr[8][4], oac[8][4];
        float m0 = -1e30f, m1 = -1e30f, l0 = 0.f, l1 = 0.f;
#pragma unroll
        for (int j = 0; j < 8; ++j)
#pragma unroll
            for (int e = 0; e < 4; ++e) oac[j][e] = 0.f;

        const int ntile = qt * 2 + 2;
        for (int kt = 0; kt < ntile; ++kt) {
            cp_wait<0>();
            __syncthreads();
            if (kt + 1 < ntile) {
                const int k1 = (kt + 1) * 64;
                const uint32_t dst = sKV + ((kt + 1) & 1) * KVSTAGE;
                const __half* srck = k + base + (size_t)k1 * DD;
                const __half* srcv = v + base + (size_t)k1 * DD;
#pragma unroll
                for (int u = 0; u < 2; ++u) {
                    const int lin = tid + u * 256;
                    const int rr = lin >> 3, cc = lin & 7;
                    const size_t go = (size_t)rr * DD + cc * 8;
                    const uint32_t so = rr * AROWB + cc * 16;
                    cp_async16(dst + so, srck + go);
                    cp_async16(dst + 64 * AROWB + so, srcv + go);
                }
                cp_commit();
            }

            const uint32_t sK = sKV + (kt & 1) * KVSTAGE;
            const uint32_t sV = sK + 64 * AROWB;
            const int k0 = kt * 64;

            // ---- scores S = Q @ K^T ----
#pragma unroll
            for (int j = 0; j < 8; ++j)
#pragma unroll
                for (int e = 0; e < 4; ++e) sfr[j][e] = 0.f;
#pragma unroll
            for (int t = 0; t < 4; ++t) {
                uint32_t qa[4];
                ldsm_x4(qa, qb + t * 32);
#pragma unroll
                for (int g = 0; g < 4; ++g) {
                    uint32_t kb[4];
                    ldsm_x4(kb, sK + (g * 16 + krow) * AROWB + t * 32 + kof);
                    mma16816h(sfr[2*g],   qa, kb);
                    mma16816h(sfr[2*g+1], qa, kb + 2);
                }
            }

            // ---- online softmax (base-2 domain, warp-local rows) ----
            const float cs = 0.1803368801111204f;   // 0.125 * log2(e)
            const int rg0 = q0 + warp * 16 + (lane >> 2);
            if (kt >= 2 * qt) {
#pragma unroll
                for (int j = 0; j < 8; ++j) {
                    const int cb = k0 + j * 8 + 2 * (lane & 3);
#pragma unroll
                    for (int e = 0; e < 4; ++e) {
                        const int cg = cb + (e & 1);
                        const int rg = rg0 + ((e >> 1) << 3);
                        const float s = sfr[j][e] * cs;
                        sfr[j][e] = (cg > rg) ? -1e30f : s;
                    }
                }
            } else {
#pragma unroll
                for (int j = 0; j < 8; ++j)
#pragma unroll
                    for (int e = 0; e < 4; ++e) sfr[j][e] *= cs;
            }
            float mx0 = -1e30f, mx1 = -1e30f;
#pragma unroll
            for (int j = 0; j < 8; ++j) {
                mx0 = fmaxf(mx0, fmaxf(sfr[j][0], sfr[j][1]));
                mx1 = fmaxf(mx1, fmaxf(sfr[j][2], sfr[j][3]));
            }
            mx0 = fmaxf(mx0, __shfl_xor_sync(0xffffffffu, mx0, 1));
            mx0 = fmaxf(mx0, __shfl_xor_sync(0xffffffffu, mx0, 2));
            mx1 = fmaxf(mx1, __shfl_xor_sync(0xffffffffu, mx1, 1));
            mx1 = fmaxf(mx1, __shfl_xor_sync(0xffffffffu, mx1, 2));
            mx0 = fmaxf(mx0, m0);
            mx1 = fmaxf(mx1, m1);
            const float al0 = exp2f(m0 - mx0);
            const float al1 = exp2f(m1 - mx1);
            m0 = mx0; m1 = mx1;
            float s0 = 0.f, s1 = 0.f;
#pragma unroll
            for (int j = 0; j < 8; ++j) {
                float p0 = exp2f(sfr[j][0] - mx0);
                float p1 = exp2f(sfr[j][1] - mx0);
                float p2 = exp2f(sfr[j][2] - mx1);
                float p3 = exp2f(sfr[j][3] - mx1);
                sfr[j][0] = p0; sfr[j][1] = p1; sfr[j][2] = p2; sfr[j][3] = p3;
                s0 += p0 + p1; s1 += p2 + p3;
            }
            s0 += __shfl_xor_sync(0xffffffffu, s0, 1);
            s0 += __shfl_xor_sync(0xffffffffu, s0, 2);
            s1 += __shfl_xor_sync(0xffffffffu, s1, 1);
            s1 += __shfl_xor_sync(0xffffffffu, s1, 2);
            l0 = l0 * al0 + s0;
            l1 = l1 * al1 + s1;
#pragma unroll
            for (int j = 0; j < 8; ++j) {
                oac[j][0] *= al0; oac[j][1] *= al0;
                oac[j][2] *= al1; oac[j][3] *= al1;
            }

            // ---- O += P @ V ----
#pragma unroll
            for (int t = 0; t < 4; ++t) {
                const float* f0 = sfr[2*t];
                const float* f1 = sfr[2*t+1];
                uint32_t pa[4];
                pa[0] = packh(f0[0], f0[1]);
                pa[1] = packh(f0[2], f0[3]);
                pa[2] = packh(f1[0], f1[1]);
                pa[3] = packh(f1[2], f1[3]);
#pragma unroll
                for (int np = 0; np < 4; ++np) {
                    uint32_t vb[4];
                    ldsm_x4_t(vb, sV + (t * 16 + vrow) * AROWB + np * 32 + vof);
                    mma16816h(oac[2*np],   pa, vb);
                    mma16816h(oac[2*np+1], pa, vb + 2);
                }
            }
        }

        // ---- write O (fp16) ----
        const float inv0 = 1.f / l0, inv1 = 1.f / l1;
        const int r0g = q0 + warp * 16 + (lane >> 2);
#pragma unroll
        for (int j = 0; j < 8; ++j) {
            const size_t off0 = base + (size_t)r0g * DD + j * 8 + 2 * (lane & 3);
            const size_t off1 = off0 + (size_t)8 * DD;
            *(__half2*)(o + off0) = __floats2half2_rn(oac[j][0] * inv0, oac[j][1] * inv0);
            *(__half2*)(o + off1) = __floats2half2_rn(oac[j][2] * inv1, oac[j][3] * inv1);
        }
    }
}

// ---------------- LayerNorm -> fp16 (standalone, for ln2) -----------------------
__global__ void ln_half_kernel(const float* __restrict__ x,
                               const float* __restrict__ g,
                               const float* __restrict__ b,
                               __half* __restrict__ y) {
    const int row = blockIdx.x;
    const int tid = threadIdx.x;
    const float* xr = x + (size_t)row * DD;

    float v[4];
    float s = 0.f, s2 = 0.f;
#pragma unroll
    for (int i = 0; i < 4; ++i) {
        v[i] = xr[tid + i * 256];
        s += v[i]; s2 += v[i] * v[i];
    }
    for (int off = 16; off > 0; off >>= 1) {
        s  += __shfl_down_sync(0xffffffffu, s,  off);
        s2 += __shfl_down_sync(0xffffffffu, s2, off);
    }
    __shared__ float rs[8], rs2[8];
    if ((tid & 31) == 0) { rs[tid >> 5] = s; rs2[tid >> 5] = s2; }
    __syncthreads();
    if (tid < 8) { s = rs[tid]; s2 = rs2[tid]; } else { s = 0.f; s2 = 0.f; }
    if (tid < 32) {
        for (int off = 4; off > 0; off >>= 1) {
            s  += __shfl_down_sync(0xffffffffu, s,  off);
            s2 += __shfl_down_sync(0xffffffffu, s2, off);
        }
        if (tid == 0) { rs[0] = s; rs2[0] = s2; }
    }
    __syncthreads();
    const float mean = rs[0] * (1.0f / DD);
    const float var  = rs2[0] * (1.0f / DD) - mean * mean;
    const float inv  = rsqrtf(var + 1e-5f);
    __half* yr = y + (size_t)row * DD;
#pragma unroll
    for (int i = 0; i < 4; ++i) {
        const int c = tid + i * 256;
        yr[c] = __float2half_rn((v[i] - mean) * inv * g[c] + b[c]);
    }
}

// ---------------- host launcher -------------------------------------------------
extern "C" void kernel_launch(void* const* d_in, const int* in_sizes, int n_in,
                              void* d_out, int out_size) {
    const float* x     = (const float*)d_in[0];
    const float* ln1_g = (const float*)d_in[1];
    const float* ln1_b = (const float*)d_in[2];
    const float* wq    = (const float*)d_in[3];
    const float* bq    = (const float*)d_in[4];
    const float* wk    = (const float*)d_in[5];
    const float* bk    = (const float*)d_in[6];
    const float* wv    = (const float*)d_in[7];
    const float* bv    = (const float*)d_in[8];
    const float* wo    = (const float*)d_in[9];
    const float* bo    = (const float*)d_in[10];
    const float* ln2_g = (const float*)d_in[11];
    const float* ln2_b = (const float*)d_in[12];
    const float* w1    = (const float*)d_in[13];
    const float* b1    = (const float*)d_in[14];
    const float* w2    = (const float*)d_in[15];
    const float* b2    = (const float*)d_in[16];
    float* out = (float*)d_out;

    __half *ph, *pq, *pk, *pv, *po, *ph2, *pact;
    __half *pwqkv, *pwo, *pw1, *pw2;
    float *padd1;
    cudaGetSymbolAddress((void**)&ph,   g_h);
    cudaGetSymbolAddress((void**)&pq,   g_q);
    cudaGetSymbolAddress((void**)&pk,   g_k);
    cudaGetSymbolAddress((void**)&pv,   g_v);
    cudaGetSymbolAddress((void**)&po,   g_o);
    cudaGetSymbolAddress((void**)&padd1,g_add1);
    cudaGetSymbolAddress((void**)&ph2,  g_h2);
    cudaGetSymbolAddress((void**)&pact, g_act);
    cudaGetSymbolAddress((void**)&pwqkv,g_wqkv);
    cudaGetSymbolAddress((void**)&pwo,  g_wo);
    cudaGetSymbolAddress((void**)&pw1,  g_w1);
    cudaGetSymbolAddress((void**)&pw2,  g_w2);

    cudaFuncSetAttribute(tc_gemm<2,false,false,true >, cudaFuncAttributeMaxDynamicSharedMemorySize, GEMM_SMEM);
    cudaFuncSetAttribute(tc_gemm<0,true, false,false>, cudaFuncAttributeMaxDynamicSharedMemorySize, GEMM_SMEM);
    cudaFuncSetAttribute(tc_gemm<2,false,true ,false>, cudaFuncAttributeMaxDynamicSharedMemorySize, GEMM_SMEM);
    cudaFuncSetAttribute(attn_mma, cudaFuncAttributeMaxDynamicSharedMemorySize, ATT_SMEM);

    dim3 gridD(DD/128, NTOK/128);
    dim3 gridF(FF/128, NTOK/128);

    // #1 fused prologue: ln1 (4096 blocks) + all weight transposes (12288 blocks)
    prologue_kernel<<<NTOK + 12288, 256>>>(x, ln1_g, ln1_b, ph,
                                           wq, wk, wv, wo, w1, w2,
                                           pwqkv, pwo, pw1, pw2);

    // #2 fused QKV GEMM (768 CTAs, SPLIT3 output routing)
    {
        dim3 grid(3*DD/128, NTOK/128);
        tc_gemm<2,false,false,true><<<grid, 256, GEMM_SMEM>>>(
            ph, pwqkv, bq, bk, bv, nullptr,
            nullptr, pq, pk, pv, NTOK, 3*DD, DD);
    }

    // #3 attention (paired q-tiles: perfectly balanced single wave)
    {
        dim3 grid(SS/256, BB*HH);   // 8 x 32 = 256 CTAs
        attn_mma<<<grid, 256, ATT_SMEM>>>(pq, pk, pv, po);
    }

    // #4 O-proj + residual: add1 = x + o@wo + bo
    tc_gemm<0,true,false,false><<<gridD, 256, GEMM_SMEM>>>(
        po, pwo, bo, nullptr, nullptr, x,
        padd1, nullptr, nullptr, nullptr, NTOK, DD, DD);

    // #5 ln2
    ln_half_kernel<<<NTOK, 256>>>(padd1, ln2_g, ln2_b, ph2);

    // #6 MLP up + gelu -> fp16
    tc_gemm<2,false,true,false><<<gridF, 256, GEMM_SMEM>>>(
        ph2, pw1, b1, nullptr, nullptr, nullptr,
        nullptr, pact, nullptr, nullptr, NTOK, FF, DD);

    // #7 MLP down + residual -> out
    tc_gemm<0,true,false,false><<<gridD, 256, GEMM_SMEM>>>(
        pact, pw2, b2, nullptr, nullptr, padd1,
        out, nullptr, nullptr, nullptr, NTOK, DD, FF);
}